// round 11
// baseline (speedup 1.0000x reference)
#include <cuda_runtime.h>
#include <cstdint>

// ---------------- problem constants ----------------
#define BB     4
#define CCH    256
#define HH     224
#define HW     50176        // 224*224
#define WSZ    7
#define SHIFTV 3
#define NHEAD  8
#define HD     32
#define WS2    49
#define WINSTR 1568         // 49*32 floats per (window,head)
static constexpr size_t QKV_PLANE = 51380224ull;   // one of q/k/v

// scratch: q,k,v in window-major layout [3][b][hn][wn][head][tok][d]
static __device__ float g_qkv[3ull * QKV_PLANE];   // 616 MB static device scratch

typedef unsigned long long ull;

__device__ __forceinline__ uint32_t f2tf32(float f) {
    uint32_t r;
    asm("cvt.rna.tf32.f32 %0, %1;" : "=r"(r) : "f"(f));
    return r;
}
__device__ __forceinline__ void mma_tf32(float* c, const uint32_t* a,
                                         const uint32_t* b) {
    asm volatile(
        "mma.sync.aligned.m16n8k8.row.col.f32.tf32.tf32.f32 "
        "{%0,%1,%2,%3}, {%4,%5,%6,%7}, {%8,%9}, {%0,%1,%2,%3};"
        : "+f"(c[0]), "+f"(c[1]), "+f"(c[2]), "+f"(c[3])
        : "r"(a[0]), "r"(a[1]), "r"(a[2]), "r"(a[3]), "r"(b[0]), "r"(b[1]));
}
__device__ __forceinline__ ull pk2(float lo, float hi) {
    ull r;
    asm("mov.b64 %0, {%1,%2};" : "=l"(r) : "f"(lo), "f"(hi));
    return r;
}
__device__ __forceinline__ void fma2(ull& d, ull a, ull b) {
    asm("fma.rn.f32x2 %0, %1, %2, %3;" : "=l"(d) : "l"(a), "l"(b), "l"(d));
}
__device__ __forceinline__ float2 upk2(ull v) {
    float2 r;
    asm("mov.b64 {%0,%1}, %2;" : "=f"(r.x), "=f"(r.y) : "l"(v));
    return r;
}

// fast exp2-based exp((s-mx)*scale): FMA-pipe only (no MUFU)
__device__ __forceinline__ float fexp_scaled(float sm_diff) {
    const float C = 0.17677669529663687f * 1.4426950408889634f;  // scale*log2e
    float y = sm_diff * C;
    y = fmaxf(y, -100.0f);
    float z = y + 12582912.0f;                    // round-to-nearest via magic
    float n = z - 12582912.0f;
    float f = y - n;                              // f in [-0.5, 0.5]
    int ni = __float_as_int(z) - 0x4B400000;      // integer part
    float p = 0.0013333558146428443f;
    p = fmaf(p, f, 0.009618129107628477f);
    p = fmaf(p, f, 0.05550410866482158f);
    p = fmaf(p, f, 0.2402265069591007f);
    p = fmaf(p, f, 0.6931471805599453f);
    p = fmaf(p, f, 1.0f);
    return __int_as_float(__float_as_int(p) + (ni << 23));
}

// =====================================================================
// Kernel 1: shifted 1x1-conv QKV GEMM on tf32 mma.sync, double-buffered.
//   CTA tile: M=128 out-channels x N=128 pixels, kb=16, K=256.
//   8 warps in 2(M) x 4(N); warp tile 64x32 = 4x4 m16n8k8 fragments.
// =====================================================================
__global__ __launch_bounds__(256, 1) void qkv_gemm(const float* __restrict__ x,
                                                   const float* __restrict__ wq,
                                                   const float* __restrict__ bq)
{
    // union: 2 x (As[16][132] + Bs[16][132]) = 8448 u32 | epilogue 64x132 f32
    __shared__ __align__(16) uint32_t buf[8448];
    __shared__ int   soff[128];
    __shared__ int   wbs[128];
    __shared__ float bias_s[128];

    const int mt  = blockIdx.x;                   // 0..5
    const int pt  = blockIdx.y;                   // 0..1567
    const int b   = pt / 392;
    const int p0  = (pt - b * 392) * 128;
    const int om  = mt * 128;
    const int tid = threadIdx.x;
    const int wid = tid >> 5;
    const int lane = tid & 31;

    if (tid < 128) {
        int p  = p0 + tid;
        int h  = p / HH, w = p - h * HH;
        int hs = h + SHIFTV; if (hs >= HH) hs -= HH;
        int ws = w + SHIFTV; if (ws >= HH) ws -= HH;
        soff[tid] = hs * HH + ws;
        int hn = h / WSZ, ri = h - hn * WSZ;
        int wn = w / WSZ, ci = w - wn * WSZ;
        int widx = (b * 32 + hn) * 32 + wn;
        wbs[tid]    = widx * 8 * WINSTR + (ri * WSZ + ci) * HD;
        bias_s[tid] = bq[om + tid];
    }
    __syncthreads();

    const float* xb = x + (size_t)b * CCH * HW;

    // warp position: 2 warps on M, 4 on N
    const int mw = wid & 1;
    const int nw = wid >> 1;
    const int grp = lane >> 2;                    // 0..7
    const int tig = lane & 3;                     // 0..3

    float acc[4][4][4];
#pragma unroll
    for (int i = 0; i < 4; ++i)
#pragma unroll
        for (int j = 0; j < 4; ++j)
#pragma unroll
            for (int r = 0; r < 4; ++r) acc[i][j][r] = 0.f;

    // load roles
    const int ao  = tid & 127;                    // A row (out-channel)
    const int acs = tid >> 7;                     // 0/1
    const int bn  = tid & 127;                    // B col (pixel)
    const int bk0 = tid >> 7;                     // 0/1
    const float* xc = xb + soff[bn];
    const float4* wrow =
        reinterpret_cast<const float4*>(wq + (size_t)(om + ao) * CCH);

    // ---- prologue: tile kt=0 -> buffer 0 ----
    {
        uint32_t* A0 = buf;
        uint32_t* B0 = buf + 2112;
#pragma unroll
        for (int s = 0; s < 2; ++s) {
            int cs = acs + s * 2;
            float4 v = wrow[cs];
            A0[(cs * 4 + 0) * 132 + ao] = f2tf32(v.x);
            A0[(cs * 4 + 1) * 132 + ao] = f2tf32(v.y);
            A0[(cs * 4 + 2) * 132 + ao] = f2tf32(v.z);
            A0[(cs * 4 + 3) * 132 + ao] = f2tf32(v.w);
        }
#pragma unroll
        for (int s = 0; s < 8; ++s) {
            int k = bk0 + s * 2;
            B0[k * 132 + bn] = f2tf32(xc[(size_t)k * HW]);
        }
    }
    __syncthreads();

    for (int kt = 0; kt < 16; ++kt) {
        uint32_t* As = buf + (kt & 1) * 4224;
        uint32_t* Bs = As + 2112;
        const bool pre = (kt < 15);

        // ---- prefetch next tile into registers ----
        float4 av[2];
        float  bv[8];
        if (pre) {
#pragma unroll
            for (int s = 0; s < 2; ++s)
                av[s] = wrow[(kt + 1) * 4 + acs + s * 2];
#pragma unroll
            for (int s = 0; s < 8; ++s)
                bv[s] = xc[(size_t)((kt + 1) * 16 + bk0 + s * 2) * HW];
        }

        // ---- MMA on current buffer ----
#pragma unroll
        for (int ks = 0; ks < 2; ++ks) {
            const int kk = ks * 8;
            uint32_t afr[4][4];
#pragma unroll
            for (int mf = 0; mf < 4; ++mf) {
                int m0 = mw * 64 + mf * 16;
                afr[mf][0] = As[(kk + tig) * 132 + m0 + grp];
                afr[mf][1] = As[(kk + tig) * 132 + m0 + grp + 8];
                afr[mf][2] = As[(kk + tig + 4) * 132 + m0 + grp];
                afr[mf][3] = As[(kk + tig + 4) * 132 + m0 + grp + 8];
            }
            uint32_t bfr[4][2];
#pragma unroll
            for (int nf = 0; nf < 4; ++nf) {
                int n0 = nw * 32 + nf * 8;
                bfr[nf][0] = Bs[(kk + tig) * 132 + n0 + grp];
                bfr[nf][1] = Bs[(kk + tig + 4) * 132 + n0 + grp];
            }
#pragma unroll
            for (int mf = 0; mf < 4; ++mf)
#pragma unroll
                for (int nf = 0; nf < 4; ++nf)
                    mma_tf32(acc[mf][nf], afr[mf], bfr[nf]);
        }

        // ---- store prefetched tile into the other buffer ----
        if (pre) {
            uint32_t* An = buf + ((kt + 1) & 1) * 4224;
            uint32_t* Bn = An + 2112;
#pragma unroll
            for (int s = 0; s < 2; ++s) {
                int cs = acs + s * 2;
                An[(cs * 4 + 0) * 132 + ao] = f2tf32(av[s].x);
                An[(cs * 4 + 1) * 132 + ao] = f2tf32(av[s].y);
                An[(cs * 4 + 2) * 132 + ao] = f2tf32(av[s].z);
                An[(cs * 4 + 3) * 132 + ao] = f2tf32(av[s].w);
            }
#pragma unroll
            for (int s = 0; s < 8; ++s) {
                int k = bk0 + s * 2;
                Bn[k * 132 + bn] = f2tf32(bv[s]);
            }
        }
        __syncthreads();
    }

    // ---- epilogue: regs -> smem transpose (+bias) -> window scatter ----
    const int qsel = om >> 8;
    float* gout = g_qkv + (size_t)qsel * QKV_PLANE;
    float* st   = reinterpret_cast<float*>(buf);  // st[n_local][132]

    const int n_loc = tid & 63;
    const int qg    = tid >> 6;                   // 0..3
    const int mm0   = om & 255;

#pragma unroll
    for (int h = 0; h < 2; ++h) {
        if ((nw >> 1) == h) {                     // this warp's n-range in half h
#pragma unroll
            for (int mf = 0; mf < 4; ++mf) {
#pragma unroll
                for (int nf = 0; nf < 4; ++nf) {
#pragma unroll
                    for (int ci = 0; ci < 4; ++ci) {
                        int m = mw * 64 + mf * 16 + grp + ((ci >> 1) << 3);
                        int n = nw * 32 + nf * 8 + tig * 2 + (ci & 1);
                        st[(n - h * 64) * 132 + m] = acc[mf][nf][ci] + bias_s[m];
                    }
                }
            }
        }
        __syncthreads();

        const int n = h * 64 + n_loc;
        const int so_base = wbs[n];
#pragma unroll
        for (int mg = 0; mg < 8; ++mg) {
            int m4 = qg * 32 + mg * 4;
            float4 v = *reinterpret_cast<const float4*>(st + n_loc * 132 + m4);
            int mm = mm0 + m4;
            *reinterpret_cast<float4*>(gout + (mm >> 5) * WINSTR + so_base + (mm & 31)) = v;
        }
        __syncthreads();
    }
}

// =====================================================================
// Kernel 2: per-(window, head) attention.
//   v2: MUFU-free softmax (poly exp2) + packed f32x2 FMA loops.
// =====================================================================
__global__ __launch_bounds__(64) void win_attn(float* __restrict__ out)
{
    __shared__ __align__(16) float sm[4704];      // Q[1568] K[1568] V[1568]

    const int bid  = blockIdx.x;                  // window*8 + head
    const int widx = bid >> 3;
    const int head = bid & 7;
    const int b    = widx >> 10;
    const int hn   = (widx >> 5) & 31;
    const int wn   = widx & 31;
    const int tid  = threadIdx.x;

    const float4* q4 = reinterpret_cast<const float4*>(g_qkv + (size_t)bid * WINSTR);
    const float4* k4 = reinterpret_cast<const float4*>(g_qkv + QKV_PLANE + (size_t)bid * WINSTR);
    const float4* v4 = reinterpret_cast<const float4*>(g_qkv + 2 * QKV_PLANE + (size_t)bid * WINSTR);
    {
        float4* s4 = reinterpret_cast<float4*>(sm);
        for (int i = tid; i < 392; i += 64) {
            s4[i]       = q4[i];
            s4[392 + i] = k4[i];
            s4[784 + i] = v4[i];
        }
    }
    __syncthreads();

    float srow[49];
    ull   oa2[16];
    float inv = 0.f;

    if (tid < 49) {
        ull q2[16];
        {
            const ulonglong2* qr =
                reinterpret_cast<const ulonglong2*>(sm + tid * HD);
#pragma unroll
            for (int i = 0; i < 8; ++i) {
                ulonglong2 t = qr[i];
                q2[2 * i]     = t.x;
                q2[2 * i + 1] = t.y;
            }
        }

        float mx = -1e30f;
#pragma unroll
        for (int j = 0; j < 49; ++j) {
            const ulonglong2* kr =
                reinterpret_cast<const ulonglong2*>(sm + 1568 + j * HD);
            ull a0 = 0ull, a1 = 0ull;
#pragma unroll
            for (int i = 0; i < 8; ++i) {
                ulonglong2 kv = kr[i];
                fma2(a0, q2[2 * i],     kv.x);
                fma2(a1, q2[2 * i + 1], kv.y);
            }
            float2 fa = upk2(a0), fb = upk2(a1);
            float s = (fa.x + fa.y) + (fb.x + fb.y);
            srow[j] = s;
            mx = fmaxf(mx, s);
        }

        float sum0 = 0.f, sum1 = 0.f;
#pragma unroll
        for (int j = 0; j < 49; ++j) {
            float e = fexp_scaled(srow[j] - mx);
            srow[j] = e;
            if (j & 1) sum1 += e; else sum0 += e;
        }
        inv = 1.f / (sum0 + sum1);

#pragma unroll
        for (int i = 0; i < 16; ++i) oa2[i] = 0ull;
#pragma unroll
        for (int j = 0; j < 49; ++j) {
            const ulonglong2* vr =
                reinterpret_cast<const ulonglong2*>(sm + 3136 + j * HD);
            ull wj2 = pk2(srow[j], srow[j]);
#pragma unroll
            for (int i = 0; i < 8; ++i) {
                ulonglong2 vv = vr[i];
                fma2(oa2[2 * i],     wj2, vv.x);
                fma2(oa2[2 * i + 1], wj2, vv.y);
            }
        }
    }
    __syncthreads();                              // all K/Q/V reads done

    if (tid < 49) {                               // stage O[tok][d], stride 33
        float* so = sm + tid * 33;
#pragma unroll
        for (int i = 0; i < 16; ++i) {
            float2 t = upk2(oa2[i]);
            so[i * 2 + 0] = t.x * inv;
            so[i * 2 + 1] = t.y * inv;
        }
    }
    __syncthreads();

    // global write with inverse roll; lanes sweep tok => 7-float coalesced runs
    const int h0 = hn * WSZ, w0 = wn * WSZ;
    float* ob = out + ((size_t)b * CCH + head * HD) * HW;
    for (int idx = tid; idx < WINSTR; idx += 64) {
        int d   = idx / WS2;
        int tok = idx - d * WS2;
        int ri  = tok / WSZ, ci = tok - ri * WSZ;
        int h = h0 + ri + SHIFTV; if (h >= HH) h -= HH;
        int w = w0 + ci + SHIFTV; if (w >= HH) w -= HH;
        ob[(size_t)d * HW + h * HH + w] = sm[tok * 33 + d];
    }
}

// =====================================================================
extern "C" void kernel_launch(void* const* d_in, const int* in_sizes, int n_in,
                              void* d_out, int out_size)
{
    const float* x  = (const float*)d_in[0];   // [4,256,224,224]
    const float* wq = (const float*)d_in[1];   // [768,256]
    const float* bq = (const float*)d_in[2];   // [768]
    float* out = (float*)d_out;                // [4,256,224,224]

    dim3 ggrid(6, 1568);                       // m-tiles fastest -> x reused in L2
    qkv_gemm<<<ggrid, 256>>>(x, wq, bq);
    win_attn<<<32768, 64>>>(out);
}

// round 12
// speedup vs baseline: 1.2258x; 1.2258x over previous
#include <cuda_runtime.h>
#include <cstdint>

// ---------------- problem constants ----------------
#define BB     4
#define CCH    256
#define HH     224
#define HW     50176        // 224*224
#define WSZ    7
#define SHIFTV 3
#define NHEAD  8
#define HD     32
#define WS2    49
#define WINSTR 1568         // 49*32 floats per (window,head)
static constexpr size_t QKV_PLANE = 51380224ull;   // one of q/k/v

// scratch: q,k,v in window-major layout [3][b][hn][wn][head][tok][d]
static __device__ float g_qkv[3ull * QKV_PLANE];   // 616 MB static device scratch

typedef unsigned long long ull;

__device__ __forceinline__ uint32_t f2tf32(float f) {
    uint32_t r;
    asm("cvt.rna.tf32.f32 %0, %1;" : "=r"(r) : "f"(f));
    return r;
}
__device__ __forceinline__ float f2tf32f(float f) {
    return __uint_as_float(f2tf32(f));
}
__device__ __forceinline__ void mma_tf32(float* c, const uint32_t* a,
                                         const uint32_t* b) {
    asm volatile(
        "mma.sync.aligned.m16n8k8.row.col.f32.tf32.tf32.f32 "
        "{%0,%1,%2,%3}, {%4,%5,%6,%7}, {%8,%9}, {%0,%1,%2,%3};"
        : "+f"(c[0]), "+f"(c[1]), "+f"(c[2]), "+f"(c[3])
        : "r"(a[0]), "r"(a[1]), "r"(a[2]), "r"(a[3]), "r"(b[0]), "r"(b[1]));
}

// fast exp2-based exp((s-mx)*scale): FMA-pipe only (no MUFU)
__device__ __forceinline__ float fexp_scaled(float sm_diff) {
    const float C = 0.17677669529663687f * 1.4426950408889634f;  // scale*log2e
    float y = sm_diff * C;
    y = fmaxf(y, -100.0f);
    float z = y + 12582912.0f;                    // round-to-nearest via magic
    float n = z - 12582912.0f;
    float f = y - n;                              // f in [-0.5, 0.5]
    int ni = __float_as_int(z) - 0x4B400000;      // integer part
    float p = 0.0013333558146428443f;
    p = fmaf(p, f, 0.009618129107628477f);
    p = fmaf(p, f, 0.05550410866482158f);
    p = fmaf(p, f, 0.2402265069591007f);
    p = fmaf(p, f, 0.6931471805599453f);
    p = fmaf(p, f, 1.0f);
    return __int_as_float(__float_as_int(p) + (ni << 23));
}

// =====================================================================
// Kernel 1: shifted 1x1-conv QKV GEMM on tf32 mma.sync (R10 version).
//   CTA tile: M=128 out-channels x N=128 pixels, kb=16, K=256.
//   8 warps in 2(M) x 4(N); warp tile 64x32 = 4x4 m16n8k8 fragments.
// =====================================================================
__global__ __launch_bounds__(256) void qkv_gemm(const float* __restrict__ x,
                                                const float* __restrict__ wq,
                                                const float* __restrict__ bq)
{
    // union: mainloop As[16][132]+Bs[16][132] (u32 tf32)  |  epilogue 64x132 f32
    __shared__ __align__(16) uint32_t buf[8448];
    __shared__ int   soff[128];
    __shared__ int   wbs[128];
    __shared__ float bias_s[128];

    uint32_t* As = buf;                 // As[k][m] : buf[k*132 + m]
    uint32_t* Bs = buf + 16 * 132;      // Bs[k][n]

    const int mt  = blockIdx.x;                   // 0..5
    const int pt  = blockIdx.y;                   // 0..1567
    const int b   = pt / 392;
    const int p0  = (pt - b * 392) * 128;
    const int om  = mt * 128;
    const int tid = threadIdx.x;
    const int wid = tid >> 5;
    const int lane = tid & 31;

    if (tid < 128) {
        int p  = p0 + tid;
        int h  = p / HH, w = p - h * HH;
        int hs = h + SHIFTV; if (hs >= HH) hs -= HH;
        int ws = w + SHIFTV; if (ws >= HH) ws -= HH;
        soff[tid] = hs * HH + ws;
        int hn = h / WSZ, ri = h - hn * WSZ;
        int wn = w / WSZ, ci = w - wn * WSZ;
        int widx = (b * 32 + hn) * 32 + wn;
        wbs[tid]    = widx * 8 * WINSTR + (ri * WSZ + ci) * HD;
        bias_s[tid] = bq[om + tid];
    }
    __syncthreads();

    const float* xb = x + (size_t)b * CCH * HW;

    // warp position: 2 warps on M, 4 on N
    const int mw = wid & 1;                       // 0..1
    const int nw = wid >> 1;                      // 0..3
    const int grp = lane >> 2;                    // 0..7
    const int tig = lane & 3;                     // 0..3

    float acc[4][4][4];
#pragma unroll
    for (int i = 0; i < 4; ++i)
#pragma unroll
        for (int j = 0; j < 4; ++j)
#pragma unroll
            for (int r = 0; r < 4; ++r) acc[i][j][r] = 0.f;

    // load roles
    const int ao  = tid & 127;                    // A row (out-channel)
    const int acs = tid >> 7;                     // 0/1
    const int bn  = tid & 127;                    // B col (pixel)
    const int bk0 = tid >> 7;                     // 0/1
    const float* xc = xb + soff[bn];
    const float4* wrow =
        reinterpret_cast<const float4*>(wq + (size_t)(om + ao) * CCH);

    for (int kt = 0; kt < 16; ++kt) {
        const int kc = kt * 16;
        // ---- A tile: w_qkv[om+o][kc..kc+16) -> As[k][m] (tf32) ----
#pragma unroll
        for (int s = 0; s < 2; ++s) {
            int cs = acs + s * 2;                 // float4 index within 16-k slab
            float4 v = wrow[kt * 4 + cs];
            As[(cs * 4 + 0) * 132 + ao] = f2tf32(v.x);
            As[(cs * 4 + 1) * 132 + ao] = f2tf32(v.y);
            As[(cs * 4 + 2) * 132 + ao] = f2tf32(v.z);
            As[(cs * 4 + 3) * 132 + ao] = f2tf32(v.w);
        }
        // ---- B tile: shifted x gather -> Bs[k][n] (tf32) ----
#pragma unroll
        for (int s = 0; s < 8; ++s) {
            int k = bk0 + s * 2;
            Bs[k * 132 + bn] = f2tf32(xc[(size_t)(kc + k) * HW]);
        }
        __syncthreads();

#pragma unroll
        for (int ks = 0; ks < 2; ++ks) {
            const int kk = ks * 8;
            uint32_t afr[4][4];
#pragma unroll
            for (int mf = 0; mf < 4; ++mf) {
                int m0 = mw * 64 + mf * 16;
                afr[mf][0] = As[(kk + tig) * 132 + m0 + grp];
                afr[mf][1] = As[(kk + tig) * 132 + m0 + grp + 8];
                afr[mf][2] = As[(kk + tig + 4) * 132 + m0 + grp];
                afr[mf][3] = As[(kk + tig + 4) * 132 + m0 + grp + 8];
            }
            uint32_t bfr[4][2];
#pragma unroll
            for (int nf = 0; nf < 4; ++nf) {
                int n0 = nw * 32 + nf * 8;
                bfr[nf][0] = Bs[(kk + tig) * 132 + n0 + grp];
                bfr[nf][1] = Bs[(kk + tig + 4) * 132 + n0 + grp];
            }
#pragma unroll
            for (int mf = 0; mf < 4; ++mf)
#pragma unroll
                for (int nf = 0; nf < 4; ++nf)
                    mma_tf32(acc[mf][nf], afr[mf], bfr[nf]);
        }
        __syncthreads();
    }

    // ---- epilogue: regs -> smem transpose (+bias) -> window scatter ----
    const int qsel = om >> 8;
    float* gout = g_qkv + (size_t)qsel * QKV_PLANE;
    float* st   = reinterpret_cast<float*>(buf);  // st[n_local][132]

    const int n_loc = tid & 63;
    const int qg    = tid >> 6;                   // 0..3
    const int mm0   = om & 255;

#pragma unroll
    for (int h = 0; h < 2; ++h) {
        if ((nw >> 1) == h) {                     // this warp's n-range in half h
#pragma unroll
            for (int mf = 0; mf < 4; ++mf) {
#pragma unroll
                for (int nf = 0; nf < 4; ++nf) {
#pragma unroll
                    for (int ci = 0; ci < 4; ++ci) {
                        int m = mw * 64 + mf * 16 + grp + ((ci >> 1) << 3);
                        int n = nw * 32 + nf * 8 + tig * 2 + (ci & 1);
                        st[(n - h * 64) * 132 + m] = acc[mf][nf][ci] + bias_s[m];
                    }
                }
            }
        }
        __syncthreads();

        const int n = h * 64 + n_loc;
        const int so_base = wbs[n];
#pragma unroll
        for (int mg = 0; mg < 8; ++mg) {
            int m4 = qg * 32 + mg * 4;
            float4 v = *reinterpret_cast<const float4*>(st + n_loc * 132 + m4);
            int mm = mm0 + m4;
            *reinterpret_cast<float4*>(gout + (mm >> 5) * WINSTR + so_base + (mm & 31)) = v;
        }
        __syncthreads();
    }
}

// =====================================================================
// Kernel 2: per-(window, head) attention on tf32 mma.sync.
//   128 threads = 4 warps; warp w owns query rows 16w..16w+15.
//   S = Q*K^T (pad 64x56), softmax in fragments, O = P*V.
// =====================================================================
__global__ __launch_bounds__(128) void win_attn(float* __restrict__ out)
{
    __shared__ __align__(16) float Qs[64 * 36];   // Q[tok][d]; reused as Os[64*33]
    __shared__ __align__(16) float Ks[32 * 68];   // K^T: [d][tok]
    __shared__ __align__(16) float Ps[64 * 60];   // P[row][key]
    __shared__ __align__(16) float Vs[56 * 36];   // V[tok][d]

    const int bid  = blockIdx.x;                  // window*8 + head
    const int widx = bid >> 3;
    const int head = bid & 7;
    const int b    = widx >> 10;
    const int hn   = (widx >> 5) & 31;
    const int wn   = widx & 31;
    const int tid  = threadIdx.x;
    const int wid  = tid >> 5;
    const int lane = tid & 31;
    const int grp  = lane >> 2;                   // 0..7
    const int tig  = lane & 3;                    // 0..3

    // ---- stage Q, K^T, V (tf32-rounded) ----
    {
        const float4* q4 = reinterpret_cast<const float4*>(g_qkv + (size_t)bid * WINSTR);
        const float4* k4 = reinterpret_cast<const float4*>(g_qkv + QKV_PLANE + (size_t)bid * WINSTR);
        const float4* v4 = reinterpret_cast<const float4*>(g_qkv + 2 * QKV_PLANE + (size_t)bid * WINSTR);
        for (int i = tid; i < 392; i += 128) {
            int tok = i >> 3, d4 = (i & 7) * 4;
            float4 qv = q4[i];
            float4 qt = make_float4(f2tf32f(qv.x), f2tf32f(qv.y),
                                    f2tf32f(qv.z), f2tf32f(qv.w));
            *reinterpret_cast<float4*>(Qs + tok * 36 + d4) = qt;
            float4 kv = k4[i];
            Ks[(d4 + 0) * 68 + tok] = f2tf32f(kv.x);
            Ks[(d4 + 1) * 68 + tok] = f2tf32f(kv.y);
            Ks[(d4 + 2) * 68 + tok] = f2tf32f(kv.z);
            Ks[(d4 + 3) * 68 + tok] = f2tf32f(kv.w);
            float4 vv = v4[i];
            float4 vt = make_float4(f2tf32f(vv.x), f2tf32f(vv.y),
                                    f2tf32f(vv.z), f2tf32f(vv.w));
            *reinterpret_cast<float4*>(Vs + tok * 36 + d4) = vt;
        }
        for (int i = tid; i < 7 * 36; i += 128)   // zero V pad rows 49..55
            Vs[49 * 36 + i] = 0.f;
    }
    __syncthreads();

    const int m0 = wid * 16;

    // ---- S = Q*K^T : 7 n-frags x 4 k-steps ----
    float c[7][4];
#pragma unroll
    for (int nf = 0; nf < 7; ++nf)
#pragma unroll
        for (int r = 0; r < 4; ++r) c[nf][r] = 0.f;

#pragma unroll
    for (int ks = 0; ks < 4; ++ks) {
        const int kk = ks * 8;
        uint32_t a[4];
        a[0] = __float_as_uint(Qs[(m0 + grp) * 36 + kk + tig]);
        a[1] = __float_as_uint(Qs[(m0 + grp + 8) * 36 + kk + tig]);
        a[2] = __float_as_uint(Qs[(m0 + grp) * 36 + kk + tig + 4]);
        a[3] = __float_as_uint(Qs[(m0 + grp + 8) * 36 + kk + tig + 4]);
#pragma unroll
        for (int nf = 0; nf < 7; ++nf) {
            uint32_t bf[2];
            bf[0] = __float_as_uint(Ks[(kk + tig) * 68 + nf * 8 + grp]);
            bf[1] = __float_as_uint(Ks[(kk + tig + 4) * 68 + nf * 8 + grp]);
            mma_tf32(c[nf], a, bf);
        }
    }

    // ---- mask pad cols, row max ----
    float mA = -1e30f, mB = -1e30f;
#pragma unroll
    for (int nf = 0; nf < 7; ++nf) {
        int col0 = nf * 8 + tig * 2;
        if (col0 > 48) { c[nf][0] = -1e30f; c[nf][2] = -1e30f; }
        if (col0 + 1 > 48) { c[nf][1] = -1e30f; c[nf][3] = -1e30f; }
        mA = fmaxf(mA, fmaxf(c[nf][0], c[nf][1]));
        mB = fmaxf(mB, fmaxf(c[nf][2], c[nf][3]));
    }
    mA = fmaxf(mA, __shfl_xor_sync(0xFFFFFFFF, mA, 1));
    mA = fmaxf(mA, __shfl_xor_sync(0xFFFFFFFF, mA, 2));
    mB = fmaxf(mB, __shfl_xor_sync(0xFFFFFFFF, mB, 1));
    mB = fmaxf(mB, __shfl_xor_sync(0xFFFFFFFF, mB, 2));

    // ---- exp + row sums + store P (tf32) ----
    float sA = 0.f, sB = 0.f;
#pragma unroll
    for (int nf = 0; nf < 7; ++nf) {
        int col0 = nf * 8 + tig * 2;
        float e0 = fexp_scaled(c[nf][0] - mA);
        float e1 = fexp_scaled(c[nf][1] - mA);
        float e2 = fexp_scaled(c[nf][2] - mB);
        float e3 = fexp_scaled(c[nf][3] - mB);
        sA += e0 + e1;
        sB += e2 + e3;
        Ps[(m0 + grp) * 60 + col0]     = f2tf32f(e0);
        Ps[(m0 + grp) * 60 + col0 + 1] = f2tf32f(e1);
        Ps[(m0 + grp + 8) * 60 + col0]     = f2tf32f(e2);
        Ps[(m0 + grp + 8) * 60 + col0 + 1] = f2tf32f(e3);
    }
    sA += __shfl_xor_sync(0xFFFFFFFF, sA, 1);
    sA += __shfl_xor_sync(0xFFFFFFFF, sA, 2);
    sB += __shfl_xor_sync(0xFFFFFFFF, sB, 1);
    sB += __shfl_xor_sync(0xFFFFFFFF, sB, 2);
    const float rA = 1.f / sA, rB = 1.f / sB;
    __syncwarp();

    // ---- O = P*V : 4 n-frags (d) x 7 k-steps (keys) ----
    float o[4][4];
#pragma unroll
    for (int nf = 0; nf < 4; ++nf)
#pragma unroll
        for (int r = 0; r < 4; ++r) o[nf][r] = 0.f;

#pragma unroll
    for (int ks = 0; ks < 7; ++ks) {
        const int kk = ks * 8;
        uint32_t a[4];
        a[0] = __float_as_uint(Ps[(m0 + grp) * 60 + kk + tig]);
        a[1] = __float_as_uint(Ps[(m0 + grp + 8) * 60 + kk + tig]);
        a[2] = __float_as_uint(Ps[(m0 + grp) * 60 + kk + tig + 4]);
        a[3] = __float_as_uint(Ps[(m0 + grp + 8) * 60 + kk + tig + 4]);
#pragma unroll
        for (int nf = 0; nf < 4; ++nf) {
            uint32_t bf[2];
            bf[0] = __float_as_uint(Vs[(kk + tig) * 36 + nf * 8 + grp]);
            bf[1] = __float_as_uint(Vs[(kk + tig + 4) * 36 + nf * 8 + grp]);
            mma_tf32(o[nf], a, bf);
        }
    }
    __syncthreads();                              // all Qs reads complete (all warps)

    // ---- normalize + stage O[row][d] into Qs region (stride 33) ----
    float* Os = Qs;
#pragma unroll
    for (int nf = 0; nf < 4; ++nf) {
        int col = nf * 8 + tig * 2;
        Os[(m0 + grp) * 33 + col]     = o[nf][0] * rA;
        Os[(m0 + grp) * 33 + col + 1] = o[nf][1] * rA;
        Os[(m0 + grp + 8) * 33 + col]     = o[nf][2] * rB;
        Os[(m0 + grp + 8) * 33 + col + 1] = o[nf][3] * rB;
    }
    __syncthreads();

    // ---- global write with inverse roll; coalesced 7-float runs ----
    const int h0 = hn * WSZ, w0 = wn * WSZ;
    float* ob = out + ((size_t)b * CCH + head * HD) * HW;
    for (int idx = tid; idx < WINSTR; idx += 128) {
        int d   = idx / WS2;
        int tok = idx - d * WS2;
        int ri  = tok / WSZ, ci = tok - ri * WSZ;
        int h = h0 + ri + SHIFTV; if (h >= HH) h -= HH;
        int w = w0 + ci + SHIFTV; if (w >= HH) w -= HH;
        ob[(size_t)d * HW + h * HH + w] = Os[tok * 33 + d];
    }
}

// =====================================================================
extern "C" void kernel_launch(void* const* d_in, const int* in_sizes, int n_in,
                              void* d_out, int out_size)
{
    const float* x  = (const float*)d_in[0];   // [4,256,224,224]
    const float* wq = (const float*)d_in[1];   // [768,256]
    const float* bq = (const float*)d_in[2];   // [768]
    float* out = (float*)d_out;                // [4,256,224,224]

    dim3 ggrid(6, 1568);                       // m-tiles fastest -> x reused in L2
    qkv_gemm<<<ggrid, 256>>>(x, wq, bq);
    win_attn<<<32768, 128>>>(out);
}

// round 13
// speedup vs baseline: 1.5629x; 1.2751x over previous
#include <cuda_runtime.h>
#include <cstdint>

// ---------------- problem constants ----------------
#define BB     4
#define CCH    256
#define HH     224
#define HW     50176        // 224*224
#define WSZ    7
#define SHIFTV 3
#define NHEAD  8
#define HD     32
#define WS2    49
#define WINSTR 1568         // 49*32 floats per (window,head)
static constexpr size_t QKV_PLANE = 51380224ull;   // one of q/k/v

// scratch: q,k,v in window-major layout [3][b][hn][wn][head][tok][d]
static __device__ float    g_qkv[3ull * QKV_PLANE];        // 616 MB
static __device__ uint32_t g_xt[(size_t)BB * CCH * HW];    // tf32 x (205 MB)
static __device__ uint32_t g_wt[768 * 256];                // tf32 w_qkv

__device__ __forceinline__ uint32_t f2tf32(float f) {
    uint32_t r;
    asm("cvt.rna.tf32.f32 %0, %1;" : "=r"(r) : "f"(f));
    return r;
}
__device__ __forceinline__ float f2tf32f(float f) {
    return __uint_as_float(f2tf32(f));
}
__device__ __forceinline__ void mma_tf32(float* c, const uint32_t* a,
                                         const uint32_t* b) {
    asm volatile(
        "mma.sync.aligned.m16n8k8.row.col.f32.tf32.tf32.f32 "
        "{%0,%1,%2,%3}, {%4,%5,%6,%7}, {%8,%9}, {%0,%1,%2,%3};"
        : "+f"(c[0]), "+f"(c[1]), "+f"(c[2]), "+f"(c[3])
        : "r"(a[0]), "r"(a[1]), "r"(a[2]), "r"(a[3]), "r"(b[0]), "r"(b[1]));
}
__device__ __forceinline__ uint32_t smaddr(const void* p) {
    uint32_t a;
    asm("{ .reg .u64 t; cvta.to.shared.u64 t, %1; cvt.u32.u64 %0, t; }"
        : "=r"(a) : "l"(p));
    return a;
}
__device__ __forceinline__ void cp16(uint32_t d, const void* s) {
    asm volatile("cp.async.ca.shared.global [%0], [%1], 16;" :: "r"(d), "l"(s));
}
__device__ __forceinline__ void cp4(uint32_t d, const void* s) {
    asm volatile("cp.async.ca.shared.global [%0], [%1], 4;" :: "r"(d), "l"(s));
}
#define CP_COMMIT() asm volatile("cp.async.commit_group;" ::: "memory")
#define CP_WAIT0()  asm volatile("cp.async.wait_group 0;" ::: "memory")

// fast exp2-based exp((s-mx)*scale): FMA-pipe only (no MUFU)
__device__ __forceinline__ float fexp_scaled(float sm_diff) {
    const float C = 0.17677669529663687f * 1.4426950408889634f;  // scale*log2e
    float y = sm_diff * C;
    y = fmaxf(y, -100.0f);
    float z = y + 12582912.0f;                    // round-to-nearest via magic
    float n = z - 12582912.0f;
    float f = y - n;                              // f in [-0.5, 0.5]
    int ni = __float_as_int(z) - 0x4B400000;      // integer part
    float p = 0.0013333558146428443f;
    p = fmaf(p, f, 0.009618129107628477f);
    p = fmaf(p, f, 0.05550410866482158f);
    p = fmaf(p, f, 0.2402265069591007f);
    p = fmaf(p, f, 0.6931471805599453f);
    p = fmaf(p, f, 1.0f);
    return __int_as_float(__float_as_int(p) + (ni << 23));
}

// =====================================================================
// Pre-pass: convert x and w_qkv to tf32 (RNA) once.
// =====================================================================
__global__ void cvt_x(const float* __restrict__ x) {
    const size_t n4 = (size_t)BB * CCH * HW / 4;
    const float4* s = reinterpret_cast<const float4*>(x);
    uint4* d = reinterpret_cast<uint4*>(g_xt);
    for (size_t i = (size_t)blockIdx.x * blockDim.x + threadIdx.x; i < n4;
         i += (size_t)gridDim.x * blockDim.x) {
        float4 v = s[i];
        uint4 t;
        t.x = f2tf32(v.x); t.y = f2tf32(v.y);
        t.z = f2tf32(v.z); t.w = f2tf32(v.w);
        d[i] = t;
    }
}
__global__ void cvt_w(const float* __restrict__ w) {
    int i = blockIdx.x * blockDim.x + threadIdx.x;
    if (i < 768 * 256 / 4) {
        float4 v = reinterpret_cast<const float4*>(w)[i];
        uint4 t;
        t.x = f2tf32(v.x); t.y = f2tf32(v.y);
        t.z = f2tf32(v.z); t.w = f2tf32(v.w);
        reinterpret_cast<uint4*>(g_wt)[i] = t;
    }
}

// =====================================================================
// Kernel 1: shifted 1x1-conv QKV GEMM, tf32 mma.sync + cp.async
//   double buffering. CTA tile M=128 x N=128, kb=16, K=256.
//   A tile: [m][k] stride 20 (conflict-free), B tile: [k][n] stride 136.
// =====================================================================
#define ASTR 20
#define BSTR 136
#define TILE_U32 4736          // 128*ASTR + 16*BSTR

__global__ __launch_bounds__(256) void qkv_gemm(const float* __restrict__ bq)
{
    // double buffer (37.9KB); reused as 64x132 f32 staging in epilogue
    __shared__ __align__(16) uint32_t buf[2 * TILE_U32];
    __shared__ int   soff[128];
    __shared__ int   wbs[128];
    __shared__ float bias_s[128];

    const int mt  = blockIdx.x;                   // 0..5
    const int pt  = blockIdx.y;                   // 0..1567
    const int b   = pt / 392;
    const int p0  = (pt - b * 392) * 128;
    const int om  = mt * 128;
    const int tid = threadIdx.x;
    const int wid = tid >> 5;
    const int lane = tid & 31;

    if (tid < 128) {
        int p  = p0 + tid;
        int h  = p / HH, w = p - h * HH;
        int hs = h + SHIFTV; if (hs >= HH) hs -= HH;
        int ws = w + SHIFTV; if (ws >= HH) ws -= HH;
        soff[tid] = hs * HH + ws;
        int hn = h / WSZ, ri = h - hn * WSZ;
        int wn = w / WSZ, ci = w - wn * WSZ;
        int widx = (b * 32 + hn) * 32 + wn;
        wbs[tid]    = widx * 8 * WINSTR + (ri * WSZ + ci) * HD;
        bias_s[tid] = bq[om + tid];
    }
    __syncthreads();

    const uint32_t buf_base = smaddr(buf);

    // loader roles
    const int bn  = tid & 127;                    // B col (pixel)
    const int bk0 = tid >> 7;                     // 0/1
    const uint32_t* xtb = g_xt + (size_t)b * CCH * HW + soff[bn];

    auto issue = [&](int kt, int sel) {
        const int kc = kt * 16;
        // A: 2 x 16B chunks per thread into [m][k] stride-20
#pragma unroll
        for (int cc = 0; cc < 2; ++cc) {
            int c = tid + cc * 256;
            int m = c >> 2, q = c & 3;
            uint32_t dst = buf_base + (uint32_t)(sel * TILE_U32 + m * ASTR + q * 4) * 4;
            cp16(dst, g_wt + (size_t)(om + m) * 256 + kc + q * 4);
        }
        // B: 8 x 4B shift-gathers per thread into [k][n] stride-136
#pragma unroll
        for (int s = 0; s < 8; ++s) {
            int k = bk0 + s * 2;
            uint32_t dst = buf_base +
                (uint32_t)(sel * TILE_U32 + 128 * ASTR + k * BSTR + bn) * 4;
            cp4(dst, xtb + (size_t)(kc + k) * HW);
        }
        CP_COMMIT();
    };

    // warp position: 2 warps on M, 4 on N
    const int mw = wid & 1;
    const int nw = wid >> 1;
    const int grp = lane >> 2;                    // 0..7
    const int tig = lane & 3;                     // 0..3

    float acc[4][4][4];
#pragma unroll
    for (int i = 0; i < 4; ++i)
#pragma unroll
        for (int j = 0; j < 4; ++j)
#pragma unroll
            for (int r = 0; r < 4; ++r) acc[i][j][r] = 0.f;

    issue(0, 0);

    for (int kt = 0; kt < 16; ++kt) {
        CP_WAIT0();
        __syncthreads();
        if (kt < 15) issue(kt + 1, (kt + 1) & 1);

        const uint32_t* As = buf + (kt & 1) * TILE_U32;       // [m][k] s20
        const uint32_t* Bs = As + 128 * ASTR;                 // [k][n] s136

#pragma unroll
        for (int ks = 0; ks < 2; ++ks) {
            const int kk = ks * 8;
            uint32_t afr[4][4];
#pragma unroll
            for (int mf = 0; mf < 4; ++mf) {
                int m0 = mw * 64 + mf * 16;
                afr[mf][0] = As[(m0 + grp) * ASTR + kk + tig];
                afr[mf][1] = As[(m0 + grp + 8) * ASTR + kk + tig];
                afr[mf][2] = As[(m0 + grp) * ASTR + kk + tig + 4];
                afr[mf][3] = As[(m0 + grp + 8) * ASTR + kk + tig + 4];
            }
            uint32_t bfr[4][2];
#pragma unroll
            for (int nf = 0; nf < 4; ++nf) {
                int n0 = nw * 32 + nf * 8;
                bfr[nf][0] = Bs[(kk + tig) * BSTR + n0 + grp];
                bfr[nf][1] = Bs[(kk + tig + 4) * BSTR + n0 + grp];
            }
#pragma unroll
            for (int mf = 0; mf < 4; ++mf)
#pragma unroll
                for (int nf = 0; nf < 4; ++nf)
                    mma_tf32(acc[mf][nf], afr[mf], bfr[nf]);
        }
    }
    __syncthreads();                              // buffers free for staging

    // ---- epilogue: regs -> smem transpose (+bias) -> window scatter ----
    const int qsel = om >> 8;
    float* gout = g_qkv + (size_t)qsel * QKV_PLANE;
    float* st   = reinterpret_cast<float*>(buf);  // st[n_local][132]

    const int n_loc = tid & 63;
    const int qg    = tid >> 6;                   // 0..3
    const int mm0   = om & 255;

#pragma unroll
    for (int h = 0; h < 2; ++h) {
        if ((nw >> 1) == h) {                     // this warp's n-range in half h
#pragma unroll
            for (int mf = 0; mf < 4; ++mf) {
#pragma unroll
                for (int nf = 0; nf < 4; ++nf) {
#pragma unroll
                    for (int ci = 0; ci < 4; ++ci) {
                        int m = mw * 64 + mf * 16 + grp + ((ci >> 1) << 3);
                        int n = nw * 32 + nf * 8 + tig * 2 + (ci & 1);
                        st[(n - h * 64) * 132 + m] = acc[mf][nf][ci] + bias_s[m];
                    }
                }
            }
        }
        __syncthreads();

        const int n = h * 64 + n_loc;
        const int so_base = wbs[n];
#pragma unroll
        for (int mg = 0; mg < 8; ++mg) {
            int m4 = qg * 32 + mg * 4;
            float4 v = *reinterpret_cast<const float4*>(st + n_loc * 132 + m4);
            int mm = mm0 + m4;
            *reinterpret_cast<float4*>(gout + (mm >> 5) * WINSTR + so_base + (mm & 31)) = v;
        }
        __syncthreads();
    }
}

// =====================================================================
// Kernel 2: per-(window, head) attention on tf32 mma.sync (R12, unchanged).
// =====================================================================
__global__ __launch_bounds__(128) void win_attn(float* __restrict__ out)
{
    __shared__ __align__(16) float Qs[64 * 36];   // Q[tok][d]; reused as Os[64*33]
    __shared__ __align__(16) float Ks[32 * 68];   // K^T: [d][tok]
    __shared__ __align__(16) float Ps[64 * 60];   // P[row][key]
    __shared__ __align__(16) float Vs[56 * 36];   // V[tok][d]

    const int bid  = blockIdx.x;                  // window*8 + head
    const int widx = bid >> 3;
    const int head = bid & 7;
    const int b    = widx >> 10;
    const int hn   = (widx >> 5) & 31;
    const int wn   = widx & 31;
    const int tid  = threadIdx.x;
    const int wid  = tid >> 5;
    const int lane = tid & 31;
    const int grp  = lane >> 2;                   // 0..7
    const int tig  = lane & 3;                    // 0..3

    // ---- stage Q, K^T, V (tf32-rounded) ----
    {
        const float4* q4 = reinterpret_cast<const float4*>(g_qkv + (size_t)bid * WINSTR);
        const float4* k4 = reinterpret_cast<const float4*>(g_qkv + QKV_PLANE + (size_t)bid * WINSTR);
        const float4* v4 = reinterpret_cast<const float4*>(g_qkv + 2 * QKV_PLANE + (size_t)bid * WINSTR);
        for (int i = tid; i < 392; i += 128) {
            int tok = i >> 3, d4 = (i & 7) * 4;
            float4 qv = q4[i];
            float4 qt = make_float4(f2tf32f(qv.x), f2tf32f(qv.y),
                                    f2tf32f(qv.z), f2tf32f(qv.w));
            *reinterpret_cast<float4*>(Qs + tok * 36 + d4) = qt;
            float4 kv = k4[i];
            Ks[(d4 + 0) * 68 + tok] = f2tf32f(kv.x);
            Ks[(d4 + 1) * 68 + tok] = f2tf32f(kv.y);
            Ks[(d4 + 2) * 68 + tok] = f2tf32f(kv.z);
            Ks[(d4 + 3) * 68 + tok] = f2tf32f(kv.w);
            float4 vv = v4[i];
            float4 vt = make_float4(f2tf32f(vv.x), f2tf32f(vv.y),
                                    f2tf32f(vv.z), f2tf32f(vv.w));
            *reinterpret_cast<float4*>(Vs + tok * 36 + d4) = vt;
        }
        for (int i = tid; i < 7 * 36; i += 128)   // zero V pad rows 49..55
            Vs[49 * 36 + i] = 0.f;
    }
    __syncthreads();

    const int m0 = wid * 16;

    // ---- S = Q*K^T : 7 n-frags x 4 k-steps ----
    float c[7][4];
#pragma unroll
    for (int nf = 0; nf < 7; ++nf)
#pragma unroll
        for (int r = 0; r < 4; ++r) c[nf][r] = 0.f;

#pragma unroll
    for (int ks = 0; ks < 4; ++ks) {
        const int kk = ks * 8;
        uint32_t a[4];
        a[0] = __float_as_uint(Qs[(m0 + grp) * 36 + kk + tig]);
        a[1] = __float_as_uint(Qs[(m0 + grp + 8) * 36 + kk + tig]);
        a[2] = __float_as_uint(Qs[(m0 + grp) * 36 + kk + tig + 4]);
        a[3] = __float_as_uint(Qs[(m0 + grp + 8) * 36 + kk + tig + 4]);
#pragma unroll
        for (int nf = 0; nf < 7; ++nf) {
            uint32_t bf[2];
            bf[0] = __float_as_uint(Ks[(kk + tig) * 68 + nf * 8 + grp]);
            bf[1] = __float_as_uint(Ks[(kk + tig + 4) * 68 + nf * 8 + grp]);
            mma_tf32(c[nf], a, bf);
        }
    }

    // ---- mask pad cols, row max ----
    float mA = -1e30f, mB = -1e30f;
#pragma unroll
    for (int nf = 0; nf < 7; ++nf) {
        int col0 = nf * 8 + tig * 2;
        if (col0 > 48) { c[nf][0] = -1e30f; c[nf][2] = -1e30f; }
        if (col0 + 1 > 48) { c[nf][1] = -1e30f; c[nf][3] = -1e30f; }
        mA = fmaxf(mA, fmaxf(c[nf][0], c[nf][1]));
        mB = fmaxf(mB, fmaxf(c[nf][2], c[nf][3]));
    }
    mA = fmaxf(mA, __shfl_xor_sync(0xFFFFFFFF, mA, 1));
    mA = fmaxf(mA, __shfl_xor_sync(0xFFFFFFFF, mA, 2));
    mB = fmaxf(mB, __shfl_xor_sync(0xFFFFFFFF, mB, 1));
    mB = fmaxf(mB, __shfl_xor_sync(0xFFFFFFFF, mB, 2));

    // ---- exp + row sums + store P (tf32) ----
    float sA = 0.f, sB = 0.f;
#pragma unroll
    for (int nf = 0; nf < 7; ++nf) {
        int col0 = nf * 8 + tig * 2;
        float e0 = fexp_scaled(c[nf][0] - mA);
        float e1 = fexp_scaled(c[nf][1] - mA);
        float e2 = fexp_scaled(c[nf][2] - mB);
        float e3 = fexp_scaled(c[nf][3] - mB);
        sA += e0 + e1;
        sB += e2 + e3;
        Ps[(m0 + grp) * 60 + col0]     = f2tf32f(e0);
        Ps[(m0 + grp) * 60 + col0 + 1] = f2tf32f(e1);
        Ps[(m0 + grp + 8) * 60 + col0]     = f2tf32f(e2);
        Ps[(m0 + grp + 8) * 60 + col0 + 1] = f2tf32f(e3);
    }
    sA += __shfl_xor_sync(0xFFFFFFFF, sA, 1);
    sA += __shfl_xor_sync(0xFFFFFFFF, sA, 2);
    sB += __shfl_xor_sync(0xFFFFFFFF, sB, 1);
    sB += __shfl_xor_sync(0xFFFFFFFF, sB, 2);
    const float rA = 1.f / sA, rB = 1.f / sB;
    __syncwarp();

    // ---- O = P*V : 4 n-frags (d) x 7 k-steps (keys) ----
    float o[4][4];
#pragma unroll
    for (int nf = 0; nf < 4; ++nf)
#pragma unroll
        for (int r = 0; r < 4; ++r) o[nf][r] = 0.f;

#pragma unroll
    for (int ks = 0; ks < 7; ++ks) {
        const int kk = ks * 8;
        uint32_t a[4];
        a[0] = __float_as_uint(Ps[(m0 + grp) * 60 + kk + tig]);
        a[1] = __float_as_uint(Ps[(m0 + grp + 8) * 60 + kk + tig]);
        a[2] = __float_as_uint(Ps[(m0 + grp) * 60 + kk + tig + 4]);
        a[3] = __float_as_uint(Ps[(m0 + grp + 8) * 60 + kk + tig + 4]);
#pragma unroll
        for (int nf = 0; nf < 4; ++nf) {
            uint32_t bf[2];
            bf[0] = __float_as_uint(Vs[(kk + tig) * 36 + nf * 8 + grp]);
            bf[1] = __float_as_uint(Vs[(kk + tig + 4) * 36 + nf * 8 + grp]);
            mma_tf32(o[nf], a, bf);
        }
    }
    __syncthreads();                              // all Qs reads complete

    // ---- normalize + stage O[row][d] into Qs region (stride 33) ----
    float* Os = Qs;
#pragma unroll
    for (int nf = 0; nf < 4; ++nf) {
        int col = nf * 8 + tig * 2;
        Os[(m0 + grp) * 33 + col]     = o[nf][0] * rA;
        Os[(m0 + grp) * 33 + col + 1] = o[nf][1] * rA;
        Os[(m0 + grp + 8) * 33 + col]     = o[nf][2] * rB;
        Os[(m0 + grp + 8) * 33 + col + 1] = o[nf][3] * rB;
    }
    __syncthreads();

    // ---- global write with inverse roll; coalesced 7-float runs ----
    const int h0 = hn * WSZ, w0 = wn * WSZ;
    float* ob = out + ((size_t)b * CCH + head * HD) * HW;
    for (int idx = tid; idx < WINSTR; idx += 128) {
        int d   = idx / WS2;
        int tok = idx - d * WS2;
        int ri  = tok / WSZ, ci = tok - ri * WSZ;
        int h = h0 + ri + SHIFTV; if (h >= HH) h -= HH;
        int w = w0 + ci + SHIFTV; if (w >= HH) w -= HH;
        ob[(size_t)d * HW + h * HH + w] = Os[tok * 33 + d];
    }
}

// =====================================================================
extern "C" void kernel_launch(void* const* d_in, const int* in_sizes, int n_in,
                              void* d_out, int out_size)
{
    const float* x  = (const float*)d_in[0];   // [4,256,224,224]
    const float* wq = (const float*)d_in[1];   // [768,256]
    const float* bq = (const float*)d_in[2];   // [768]
    float* out = (float*)d_out;                // [4,256,224,224]

    cvt_x<<<12544, 256>>>(x);
    cvt_w<<<192, 256>>>(wq);
    dim3 ggrid(6, 1568);                       // m-tiles fastest -> x reused in L2
    qkv_gemm<<<ggrid, 256>>>(bq);
    win_attn<<<32768, 128>>>(out);
}

// round 14
// speedup vs baseline: 1.6523x; 1.0572x over previous
#include <cuda_runtime.h>
#include <cstdint>

// ---------------- problem constants ----------------
#define BB     4
#define CCH    256
#define HH     224
#define HW     50176        // 224*224
#define WSZ    7
#define SHIFTV 3
#define NHEAD  8
#define HD     32
#define WS2    49
#define WINSTR 1568         // 49*32 floats per (window,head)
static constexpr size_t QKV_PLANE = 51380224ull;   // one of q/k/v

// scratch: q,k,v in window-major layout [3][b][hn][wn][head][tok][d]
static __device__ float    g_qkv[3ull * QKV_PLANE];        // 616 MB
static __device__ uint32_t g_xt[(size_t)BB * CCH * HW];    // tf32 x, pre-rolled
static __device__ uint32_t g_wt[768 * 256];                // tf32 w_qkv

__device__ __forceinline__ uint32_t f2tf32(float f) {
    uint32_t r;
    asm("cvt.rna.tf32.f32 %0, %1;" : "=r"(r) : "f"(f));
    return r;
}
__device__ __forceinline__ float f2tf32f(float f) {
    return __uint_as_float(f2tf32(f));
}
__device__ __forceinline__ void mma_tf32(float* c, const uint32_t* a,
                                         const uint32_t* b) {
    asm volatile(
        "mma.sync.aligned.m16n8k8.row.col.f32.tf32.tf32.f32 "
        "{%0,%1,%2,%3}, {%4,%5,%6,%7}, {%8,%9}, {%0,%1,%2,%3};"
        : "+f"(c[0]), "+f"(c[1]), "+f"(c[2]), "+f"(c[3])
        : "r"(a[0]), "r"(a[1]), "r"(a[2]), "r"(a[3]), "r"(b[0]), "r"(b[1]));
}
__device__ __forceinline__ uint32_t smaddr(const void* p) {
    uint32_t a;
    asm("{ .reg .u64 t; cvta.to.shared.u64 t, %1; cvt.u32.u64 %0, t; }"
        : "=r"(a) : "l"(p));
    return a;
}
__device__ __forceinline__ void cp16(uint32_t d, const void* s) {
    asm volatile("cp.async.ca.shared.global [%0], [%1], 16;" :: "r"(d), "l"(s));
}
#define CP_COMMIT() asm volatile("cp.async.commit_group;" ::: "memory")
#define CP_WAIT0()  asm volatile("cp.async.wait_group 0;" ::: "memory")
__device__ __forceinline__ void ldsm4(uint32_t& r0, uint32_t& r1,
                                      uint32_t& r2, uint32_t& r3, uint32_t a) {
    asm volatile("ldmatrix.sync.aligned.m8n8.x4.shared.b16 {%0,%1,%2,%3}, [%4];"
                 : "=r"(r0), "=r"(r1), "=r"(r2), "=r"(r3) : "r"(a));
}

// fast exp2-based exp((s-mx)*scale): FMA-pipe only (no MUFU)
__device__ __forceinline__ float fexp_scaled(float sm_diff) {
    const float C = 0.17677669529663687f * 1.4426950408889634f;  // scale*log2e
    float y = sm_diff * C;
    y = fmaxf(y, -100.0f);
    float z = y + 12582912.0f;                    // round-to-nearest via magic
    float n = z - 12582912.0f;
    float f = y - n;                              // f in [-0.5, 0.5]
    int ni = __float_as_int(z) - 0x4B400000;      // integer part
    float p = 0.0013333558146428443f;
    p = fmaf(p, f, 0.009618129107628477f);
    p = fmaf(p, f, 0.05550410866482158f);
    p = fmaf(p, f, 0.2402265069591007f);
    p = fmaf(p, f, 0.6931471805599453f);
    p = fmaf(p, f, 1.0f);
    return __int_as_float(__float_as_int(p) + (ni << 23));
}

// =====================================================================
// Pre-pass: x -> tf32 WITH the spatial roll folded in:
//   g_xt[b][c][h*W+w] = tf32( x[b][c][(h+3)%224][(w+3)%224] )
// Output contiguous; reads are 4-scalar gathers (mostly contiguous).
// =====================================================================
__global__ void cvt_x(const float* __restrict__ x) {
    const size_t n4 = (size_t)BB * CCH * HW / 4;
    uint4* d = reinterpret_cast<uint4*>(g_xt);
    for (size_t i = (size_t)blockIdx.x * blockDim.x + threadIdx.x; i < n4;
         i += (size_t)gridDim.x * blockDim.x) {
        size_t base = i * 4;
        int plane = (int)(base / HW);             // b*C + c
        int p     = (int)(base - (size_t)plane * HW);
        const float* pl = x + (size_t)plane * HW;
        int h = p / HH, w = p - h * HH;
        uint32_t t[4];
#pragma unroll
        for (int j = 0; j < 4; ++j) {
            int hs = h + SHIFTV; if (hs >= HH) hs -= HH;
            int ws = w + SHIFTV; if (ws >= HH) ws -= HH;
            t[j] = f2tf32(pl[hs * HH + ws]);
            if (++w == HH) { w = 0; ++h; }
        }
        d[i] = make_uint4(t[0], t[1], t[2], t[3]);
    }
}
__global__ void cvt_w(const float* __restrict__ w) {
    int i = blockIdx.x * blockDim.x + threadIdx.x;
    if (i < 768 * 256 / 4) {
        float4 v = reinterpret_cast<const float4*>(w)[i];
        uint4 t;
        t.x = f2tf32(v.x); t.y = f2tf32(v.y);
        t.z = f2tf32(v.z); t.w = f2tf32(v.w);
        reinterpret_cast<uint4*>(g_wt)[i] = t;
    }
}

// =====================================================================
// Kernel 1: shifted 1x1-conv QKV GEMM, tf32 mma.sync + cp.async
//   double buffering. CTA tile M=128 x N=128, kb=16, K=256.
//   A: [m][k] stride 20 (ldmatrix frags), B: [k][n] stride 136.
//   All tile loads are cp16 (B is contiguous thanks to pre-rolled g_xt).
// =====================================================================
#define ASTR 20
#define BSTR 136
#define TILE_U32 4736          // 128*ASTR + 16*BSTR

__global__ __launch_bounds__(256) void qkv_gemm(const float* __restrict__ bq)
{
    // double buffer (37.9KB); reused as 64x132 f32 staging in epilogue
    __shared__ __align__(16) uint32_t buf[2 * TILE_U32];
    __shared__ int   wbs[128];
    __shared__ float bias_s[128];

    const int mt  = blockIdx.x;                   // 0..5
    const int pt  = blockIdx.y;                   // 0..1567
    const int b   = pt / 392;
    const int p0  = (pt - b * 392) * 128;
    const int om  = mt * 128;
    const int tid = threadIdx.x;
    const int wid = tid >> 5;
    const int lane = tid & 31;

    if (tid < 128) {
        int p  = p0 + tid;
        int h  = p / HH, w = p - h * HH;
        int hn = h / WSZ, ri = h - hn * WSZ;
        int wn = w / WSZ, ci = w - wn * WSZ;
        int widx = (b * 32 + hn) * 32 + wn;
        wbs[tid]    = widx * 8 * WINSTR + (ri * WSZ + ci) * HD;
        bias_s[tid] = bq[om + tid];
    }
    __syncthreads();

    const uint32_t buf_base = smaddr(buf);

    // loader roles (all cp16)
    const int am = tid >> 1;                      // A row pair base: m = c>>2
    const int bk = tid >> 5;                      // not used directly; see issue
    (void)bk;

    auto issue = [&](int kt, int sel) {
        const int kc = kt * 16;
        // A: 512 chunks [m][k/4]: c = tid + 256*cc, m = c>>2, q = c&3
#pragma unroll
        for (int cc = 0; cc < 2; ++cc) {
            int c = tid + cc * 256;
            int m = c >> 2, q = c & 3;
            uint32_t dst = buf_base + (uint32_t)(sel * TILE_U32 + m * ASTR + q * 4) * 4;
            cp16(dst, g_wt + (size_t)(om + m) * 256 + kc + q * 4);
        }
        // B: 512 chunks [k][n/4]: c = tid + 256*cc, k = c>>5, n4 = (c&31)*4
#pragma unroll
        for (int cc = 0; cc < 2; ++cc) {
            int c = tid + cc * 256;
            int k = c >> 5, n4 = (c & 31) * 4;
            uint32_t dst = buf_base +
                (uint32_t)(sel * TILE_U32 + 128 * ASTR + k * BSTR + n4) * 4;
            cp16(dst, g_xt + (size_t)(b * CCH + kc + k) * HW + p0 + n4);
        }
        CP_COMMIT();
    };

    // warp position: 2 warps on M, 4 on N
    const int mw = wid & 1;
    const int nw = wid >> 1;
    const int grp = lane >> 2;                    // 0..7
    const int tig = lane & 3;                     // 0..3

    // ldmatrix lane offset (bytes): row = (lane&7) + ((lane>>4)<<3), halfcol
    const uint32_t lds_off =
        (uint32_t)(((lane & 7) + ((lane >> 4) << 3)) * (ASTR * 4) +
                   ((lane >> 3) & 1) * 16);

    float acc[4][4][4];
#pragma unroll
    for (int i = 0; i < 4; ++i)
#pragma unroll
        for (int j = 0; j < 4; ++j)
#pragma unroll
            for (int r = 0; r < 4; ++r) acc[i][j][r] = 0.f;

    issue(0, 0);

    for (int kt = 0; kt < 16; ++kt) {
        CP_WAIT0();
        __syncthreads();
        if (kt < 15) issue(kt + 1, (kt + 1) & 1);

        const uint32_t Abase = buf_base + (uint32_t)((kt & 1) * TILE_U32) * 4;
        const uint32_t* Bs = buf + (kt & 1) * TILE_U32 + 128 * ASTR;

#pragma unroll
        for (int ks = 0; ks < 2; ++ks) {
            const int kk = ks * 8;
            uint32_t afr[4][4];
#pragma unroll
            for (int mf = 0; mf < 4; ++mf) {
                int m0 = mw * 64 + mf * 16;
                uint32_t addr = Abase + (uint32_t)m0 * (ASTR * 4) +
                                (uint32_t)kk * 4 + lds_off;
                uint32_t r0, r1, r2, r3;
                ldsm4(r0, r1, r2, r3, addr);
                afr[mf][0] = r0; afr[mf][1] = r2;   // (grp,tig),(grp+8,tig)
                afr[mf][2] = r1; afr[mf][3] = r3;   // (grp,tig+4),(grp+8,tig+4)
            }
            uint32_t bfr[4][2];
#pragma unroll
            for (int nf = 0; nf < 4; ++nf) {
                int n0 = nw * 32 + nf * 8;
                bfr[nf][0] = Bs[(kk + tig) * BSTR + n0 + grp];
                bfr[nf][1] = Bs[(kk + tig + 4) * BSTR + n0 + grp];
            }
#pragma unroll
            for (int mf = 0; mf < 4; ++mf)
#pragma unroll
                for (int nf = 0; nf < 4; ++nf)
                    mma_tf32(acc[mf][nf], afr[mf], bfr[nf]);
        }
    }
    __syncthreads();                              // buffers free for staging

    // ---- epilogue: regs -> smem transpose (+bias) -> window scatter ----
    const int qsel = om >> 8;
    float* gout = g_qkv + (size_t)qsel * QKV_PLANE;
    float* st   = reinterpret_cast<float*>(buf);  // st[n_local][132]

    const int n_loc = tid & 63;
    const int qg    = tid >> 6;                   // 0..3
    const int mm0   = om & 255;

#pragma unroll
    for (int h = 0; h < 2; ++h) {
        if ((nw >> 1) == h) {                     // this warp's n-range in half h
#pragma unroll
            for (int mf = 0; mf < 4; ++mf) {
#pragma unroll
                for (int nf = 0; nf < 4; ++nf) {
#pragma unroll
                    for (int ci = 0; ci < 4; ++ci) {
                        int m = mw * 64 + mf * 16 + grp + ((ci >> 1) << 3);
                        int n = nw * 32 + nf * 8 + tig * 2 + (ci & 1);
                        st[(n - h * 64) * 132 + m] = acc[mf][nf][ci] + bias_s[m];
                    }
                }
            }
        }
        __syncthreads();

        const int n = h * 64 + n_loc;
        const int so_base = wbs[n];
#pragma unroll
        for (int mg = 0; mg < 8; ++mg) {
            int m4 = qg * 32 + mg * 4;
            float4 v = *reinterpret_cast<const float4*>(st + n_loc * 132 + m4);
            int mm = mm0 + m4;
            *reinterpret_cast<float4*>(gout + (mm >> 5) * WINSTR + so_base + (mm & 31)) = v;
        }
        __syncthreads();
    }
}

// =====================================================================
// Kernel 2: per-(window, head) attention on tf32 mma.sync (unchanged).
// =====================================================================
__global__ __launch_bounds__(128) void win_attn(float* __restrict__ out)
{
    __shared__ __align__(16) float Qs[64 * 36];   // Q[tok][d]; reused as Os[64*33]
    __shared__ __align__(16) float Ks[32 * 68];   // K^T: [d][tok]
    __shared__ __align__(16) float Ps[64 * 60];   // P[row][key]
    __shared__ __align__(16) float Vs[56 * 36];   // V[tok][d]

    const int bid  = blockIdx.x;                  // window*8 + head
    const int widx = bid >> 3;
    const int head = bid & 7;
    const int b    = widx >> 10;
    const int hn   = (widx >> 5) & 31;
    const int wn   = widx & 31;
    const int tid  = threadIdx.x;
    const int wid  = tid >> 5;
    const int lane = tid & 31;
    const int grp  = lane >> 2;                   // 0..7
    const int tig  = lane & 3;                    // 0..3

    // ---- stage Q, K^T, V (tf32-rounded) ----
    {
        const float4* q4 = reinterpret_cast<const float4*>(g_qkv + (size_t)bid * WINSTR);
        const float4* k4 = reinterpret_cast<const float4*>(g_qkv + QKV_PLANE + (size_t)bid * WINSTR);
        const float4* v4 = reinterpret_cast<const float4*>(g_qkv + 2 * QKV_PLANE + (size_t)bid * WINSTR);
        for (int i = tid; i < 392; i += 128) {
            int tok = i >> 3, d4 = (i & 7) * 4;
            float4 qv = q4[i];
            float4 qt = make_float4(f2tf32f(qv.x), f2tf32f(qv.y),
                                    f2tf32f(qv.z), f2tf32f(qv.w));
            *reinterpret_cast<float4*>(Qs + tok * 36 + d4) = qt;
            float4 kv = k4[i];
            Ks[(d4 + 0) * 68 + tok] = f2tf32f(kv.x);
            Ks[(d4 + 1) * 68 + tok] = f2tf32f(kv.y);
            Ks[(d4 + 2) * 68 + tok] = f2tf32f(kv.z);
            Ks[(d4 + 3) * 68 + tok] = f2tf32f(kv.w);
            float4 vv = v4[i];
            float4 vt = make_float4(f2tf32f(vv.x), f2tf32f(vv.y),
                                    f2tf32f(vv.z), f2tf32f(vv.w));
            *reinterpret_cast<float4*>(Vs + tok * 36 + d4) = vt;
        }
        for (int i = tid; i < 7 * 36; i += 128)   // zero V pad rows 49..55
            Vs[49 * 36 + i] = 0.f;
    }
    __syncthreads();

    const int m0 = wid * 16;

    // ---- S = Q*K^T : 7 n-frags x 4 k-steps ----
    float c[7][4];
#pragma unroll
    for (int nf = 0; nf < 7; ++nf)
#pragma unroll
        for (int r = 0; r < 4; ++r) c[nf][r] = 0.f;

#pragma unroll
    for (int ks = 0; ks < 4; ++ks) {
        const int kk = ks * 8;
        uint32_t a[4];
        a[0] = __float_as_uint(Qs[(m0 + grp) * 36 + kk + tig]);
        a[1] = __float_as_uint(Qs[(m0 + grp + 8) * 36 + kk + tig]);
        a[2] = __float_as_uint(Qs[(m0 + grp) * 36 + kk + tig + 4]);
        a[3] = __float_as_uint(Qs[(m0 + grp + 8) * 36 + kk + tig + 4]);
#pragma unroll
        for (int nf = 0; nf < 7; ++nf) {
            uint32_t bf[2];
            bf[0] = __float_as_uint(Ks[(kk + tig) * 68 + nf * 8 + grp]);
            bf[1] = __float_as_uint(Ks[(kk + tig + 4) * 68 + nf * 8 + grp]);
            mma_tf32(c[nf], a, bf);
        }
    }

    // ---- mask pad cols, row max ----
    float mA = -1e30f, mB = -1e30f;
#pragma unroll
    for (int nf = 0; nf < 7; ++nf) {
        int col0 = nf * 8 + tig * 2;
        if (col0 > 48) { c[nf][0] = -1e30f; c[nf][2] = -1e30f; }
        if (col0 + 1 > 48) { c[nf][1] = -1e30f; c[nf][3] = -1e30f; }
        mA = fmaxf(mA, fmaxf(c[nf][0], c[nf][1]));
        mB = fmaxf(mB, fmaxf(c[nf][2], c[nf][3]));
    }
    mA = fmaxf(mA, __shfl_xor_sync(0xFFFFFFFF, mA, 1));
    mA = fmaxf(mA, __shfl_xor_sync(0xFFFFFFFF, mA, 2));
    mB = fmaxf(mB, __shfl_xor_sync(0xFFFFFFFF, mB, 1));
    mB = fmaxf(mB, __shfl_xor_sync(0xFFFFFFFF, mB, 2));

    // ---- exp + row sums + store P (tf32) ----
    float sA = 0.f, sB = 0.f;
#pragma unroll
    for (int nf = 0; nf < 7; ++nf) {
        int col0 = nf * 8 + tig * 2;
        float e0 = fexp_scaled(c[nf][0] - mA);
        float e1 = fexp_scaled(c[nf][1] - mA);
        float e2 = fexp_scaled(c[nf][2] - mB);
        float e3 = fexp_scaled(c[nf][3] - mB);
        sA += e0 + e1;
        sB += e2 + e3;
        Ps[(m0 + grp) * 60 + col0]     = f2tf32f(e0);
        Ps[(m0 + grp) * 60 + col0 + 1] = f2tf32f(e1);
        Ps[(m0 + grp + 8) * 60 + col0]     = f2tf32f(e2);
        Ps[(m0 + grp + 8) * 60 + col0 + 1] = f2tf32f(e3);
    }
    sA += __shfl_xor_sync(0xFFFFFFFF, sA, 1);
    sA += __shfl_xor_sync(0xFFFFFFFF, sA, 2);
    sB += __shfl_xor_sync(0xFFFFFFFF, sB, 1);
    sB += __shfl_xor_sync(0xFFFFFFFF, sB, 2);
    const float rA = 1.f / sA, rB = 1.f / sB;
    __syncwarp();

    // ---- O = P*V : 4 n-frags (d) x 7 k-steps (keys) ----
    float o[4][4];
#pragma unroll
    for (int nf = 0; nf < 4; ++nf)
#pragma unroll
        for (int r = 0; r < 4; ++r) o[nf][r] = 0.f;

#pragma unroll
    for (int ks = 0; ks < 7; ++ks) {
        const int kk = ks * 8;
        uint32_t a[4];
        a[0] = __float_as_uint(Ps[(m0 + grp) * 60 + kk + tig]);
        a[1] = __float_as_uint(Ps[(m0 + grp + 8) * 60 + kk + tig]);
        a[2] = __float_as_uint(Ps[(m0 + grp) * 60 + kk + tig + 4]);
        a[3] = __float_as_uint(Ps[(m0 + grp + 8) * 60 + kk + tig + 4]);
#pragma unroll
        for (int nf = 0; nf < 4; ++nf) {
            uint32_t bf[2];
            bf[0] = __float_as_uint(Vs[(kk + tig) * 36 + nf * 8 + grp]);
            bf[1] = __float_as_uint(Vs[(kk + tig + 4) * 36 + nf * 8 + grp]);
            mma_tf32(o[nf], a, bf);
        }
    }
    __syncthreads();                              // all Qs reads complete

    // ---- normalize + stage O[row][d] into Qs region (stride 33) ----
    float* Os = Qs;
#pragma unroll
    for (int nf = 0; nf < 4; ++nf) {
        int col = nf * 8 + tig * 2;
        Os[(m0 + grp) * 33 + col]     = o[nf][0] * rA;
        Os[(m0 + grp) * 33 + col + 1] = o[nf][1] * rA;
        Os[(m0 + grp + 8) * 33 + col]     = o[nf][2] * rB;
        Os[(m0 + grp + 8) * 33 + col + 1] = o[nf][3] * rB;
    }
    __syncthreads();

    // ---- global write with inverse roll; coalesced 7-float runs ----
    const int h0 = hn * WSZ, w0 = wn * WSZ;
    float* ob = out + ((size_t)b * CCH + head * HD) * HW;
    for (int idx = tid; idx < WINSTR; idx += 128) {
        int d   = idx / WS2;
        int tok = idx - d * WS2;
        int ri  = tok / WSZ, ci = tok - ri * WSZ;
        int h = h0 + ri + SHIFTV; if (h >= HH) h -= HH;
        int w = w0 + ci + SHIFTV; if (w >= HH) w -= HH;
        ob[(size_t)d * HW + h * HH + w] = Os[tok * 33 + d];
    }
}

// =====================================================================
extern "C" void kernel_launch(void* const* d_in, const int* in_sizes, int n_in,
                              void* d_out, int out_size)
{
    const float* x  = (const float*)d_in[0];   // [4,256,224,224]
    const float* wq = (const float*)d_in[1];   // [768,256]
    const float* bq = (const float*)d_in[2];   // [768]
    float* out = (float*)d_out;                // [4,256,224,224]

    cvt_x<<<12544, 256>>>(x);
    cvt_w<<<192, 256>>>(wq);
    dim3 ggrid(6, 1568);                       // m-tiles fastest -> x reused in L2
    qkv_gemm<<<ggrid, 256>>>(bq);
    win_attn<<<32768, 128>>>(out);
}

// round 16
// speedup vs baseline: 1.7070x; 1.0331x over previous
#include <cuda_runtime.h>
#include <cstdint>

// ---------------- problem constants ----------------
#define BB     4
#define CCH    256
#define HH     224
#define HW     50176        // 224*224
#define WSZ    7
#define SHIFTV 3
#define NHEAD  8
#define HD     32
#define WS2    49
#define WINSTR 1568         // 49*32 floats per (window,head)
static constexpr size_t QKV_PLANE = 51380224ull;   // one of q/k/v

// scratch: q,k,v (tf32-rounded f32) in window-major [3][b][hn][wn][head][tok][d]
static __device__ float    g_qkv[3ull * QKV_PLANE];        // 616 MB
static __device__ uint32_t g_xt[(size_t)BB * CCH * HW];    // tf32 x (plain)
static __device__ uint32_t g_wt[768 * 256];                // tf32 w_qkv

__device__ __forceinline__ uint32_t f2tf32(float f) {
    uint32_t r;
    asm("cvt.rna.tf32.f32 %0, %1;" : "=r"(r) : "f"(f));
    return r;
}
__device__ __forceinline__ float f2tf32f(float f) {
    return __uint_as_float(f2tf32(f));
}
__device__ __forceinline__ void mma_tf32(float* c, const uint32_t* a,
                                         const uint32_t* b) {
    asm volatile(
        "mma.sync.aligned.m16n8k8.row.col.f32.tf32.tf32.f32 "
        "{%0,%1,%2,%3}, {%4,%5,%6,%7}, {%8,%9}, {%0,%1,%2,%3};"
        : "+f"(c[0]), "+f"(c[1]), "+f"(c[2]), "+f"(c[3])
        : "r"(a[0]), "r"(a[1]), "r"(a[2]), "r"(a[3]), "r"(b[0]), "r"(b[1]));
}
__device__ __forceinline__ uint32_t smaddr(const void* p) {
    uint32_t a;
    asm("{ .reg .u64 t; cvta.to.shared.u64 t, %1; cvt.u32.u64 %0, t; }"
        : "=r"(a) : "l"(p));
    return a;
}
__device__ __forceinline__ void cp16(uint32_t d, const void* s) {
    asm volatile("cp.async.ca.shared.global [%0], [%1], 16;" :: "r"(d), "l"(s));
}
#define CP_COMMIT() asm volatile("cp.async.commit_group;" ::: "memory")
#define CP_WAIT0()  asm volatile("cp.async.wait_group 0;" ::: "memory")
__device__ __forceinline__ void ldsm4(uint32_t& r0, uint32_t& r1,
                                      uint32_t& r2, uint32_t& r3, uint32_t a) {
    asm volatile("ldmatrix.sync.aligned.m8n8.x4.shared.b16 {%0,%1,%2,%3}, [%4];"
                 : "=r"(r0), "=r"(r1), "=r"(r2), "=r"(r3) : "r"(a));
}

// fast exp2-based exp((s-mx)*scale): FMA-pipe only (no MUFU)
__device__ __forceinline__ float fexp_scaled(float sm_diff) {
    const float C = 0.17677669529663687f * 1.4426950408889634f;  // scale*log2e
    float y = sm_diff * C;
    y = fmaxf(y, -100.0f);
    float z = y + 12582912.0f;                    // round-to-nearest via magic
    float n = z - 12582912.0f;
    float f = y - n;                              // f in [-0.5, 0.5]
    int ni = __float_as_int(z) - 0x4B400000;      // integer part
    float p = 0.0013333558146428443f;
    p = fmaf(p, f, 0.009618129107628477f);
    p = fmaf(p, f, 0.05550410866482158f);
    p = fmaf(p, f, 0.2402265069591007f);
    p = fmaf(p, f, 0.6931471805599453f);
    p = fmaf(p, f, 1.0f);
    return __int_as_float(__float_as_int(p) + (ni << 23));
}

// =====================================================================
// Pre-pass: plain contiguous tf32 converts (roll folded into wbs).
// =====================================================================
__global__ void cvt_x(const float* __restrict__ x) {
    const size_t n4 = (size_t)BB * CCH * HW / 4;
    const float4* s = reinterpret_cast<const float4*>(x);
    uint4* d = reinterpret_cast<uint4*>(g_xt);
    for (size_t i = (size_t)blockIdx.x * blockDim.x + threadIdx.x; i < n4;
         i += (size_t)gridDim.x * blockDim.x) {
        float4 v = s[i];
        d[i] = make_uint4(f2tf32(v.x), f2tf32(v.y), f2tf32(v.z), f2tf32(v.w));
    }
}
__global__ void cvt_w(const float* __restrict__ w) {
    int i = blockIdx.x * blockDim.x + threadIdx.x;
    if (i < 768 * 256 / 4) {
        float4 v = reinterpret_cast<const float4*>(w)[i];
        reinterpret_cast<uint4*>(g_wt)[i] =
            make_uint4(f2tf32(v.x), f2tf32(v.y), f2tf32(v.z), f2tf32(v.w));
    }
}

// =====================================================================
// Kernel 1: QKV GEMM, tf32 mma.sync + cp.async double buffering.
//   CTA tile M=128 x N=128, kb=16, K=256. Roll folded into wbs.
//   Epilogue stores tf32-rounded (bias included) to window-major scratch.
// =====================================================================
#define ASTR 20
#define BSTR 136
#define TILE_U32 4736          // 128*ASTR + 16*BSTR

__global__ __launch_bounds__(256) void qkv_gemm(const float* __restrict__ bq)
{
    __shared__ __align__(16) uint32_t buf[2 * TILE_U32];
    __shared__ int   wbs[128];
    __shared__ float bias_s[128];

    const int mt  = blockIdx.x;                   // 0..5
    const int pt  = blockIdx.y;                   // 0..1567
    const int b   = pt / 392;
    const int p0  = (pt - b * 392) * 128;
    const int om  = mt * 128;
    const int tid = threadIdx.x;
    const int wid = tid >> 5;
    const int lane = tid & 31;

    if (tid < 128) {
        int p  = p0 + tid;
        int h  = p / HH, w = p - h * HH;
        int hx = h - SHIFTV; if (hx < 0) hx += HH;   // shifted-back coords
        int wx = w - SHIFTV; if (wx < 0) wx += HH;
        int hn = hx / WSZ, ri = hx - hn * WSZ;
        int wn = wx / WSZ, ci = wx - wn * WSZ;
        int widx = (b * 32 + hn) * 32 + wn;
        wbs[tid]    = widx * 8 * WINSTR + (ri * WSZ + ci) * HD;
        bias_s[tid] = bq[om + tid];
    }
    __syncthreads();

    const uint32_t buf_base = smaddr(buf);

    auto issue = [&](int kt, int sel) {
        const int kc = kt * 16;
#pragma unroll
        for (int cc = 0; cc < 2; ++cc) {          // A: [m][k] stride 20
            int c = tid + cc * 256;
            int m = c >> 2, q = c & 3;
            uint32_t dst = buf_base + (uint32_t)(sel * TILE_U32 + m * ASTR + q * 4) * 4;
            cp16(dst, g_wt + (size_t)(om + m) * 256 + kc + q * 4);
        }
#pragma unroll
        for (int cc = 0; cc < 2; ++cc) {          // B: [k][n] stride 136
            int c = tid + cc * 256;
            int k = c >> 5, n4 = (c & 31) * 4;
            uint32_t dst = buf_base +
                (uint32_t)(sel * TILE_U32 + 128 * ASTR + k * BSTR + n4) * 4;
            cp16(dst, g_xt + (size_t)(b * CCH + kc + k) * HW + p0 + n4);
        }
        CP_COMMIT();
    };

    const int mw = wid & 1;
    const int nw = wid >> 1;
    const int grp = lane >> 2;
    const int tig = lane & 3;

    const uint32_t lds_off =
        (uint32_t)(((lane & 7) + ((lane >> 4) << 3)) * (ASTR * 4) +
                   ((lane >> 3) & 1) * 16);

    float acc[4][4][4];
#pragma unroll
    for (int i = 0; i < 4; ++i)
#pragma unroll
        for (int j = 0; j < 4; ++j)
#pragma unroll
            for (int r = 0; r < 4; ++r) acc[i][j][r] = 0.f;

    issue(0, 0);

    for (int kt = 0; kt < 16; ++kt) {
        CP_WAIT0();
        __syncthreads();
        if (kt < 15) issue(kt + 1, (kt + 1) & 1);

        const uint32_t Abase = buf_base + (uint32_t)((kt & 1) * TILE_U32) * 4;
        const uint32_t* Bs = buf + (kt & 1) * TILE_U32 + 128 * ASTR;

#pragma unroll
        for (int ks = 0; ks < 2; ++ks) {
            const int kk = ks * 8;
            uint32_t afr[4][4];
#pragma unroll
            for (int mf = 0; mf < 4; ++mf) {
                int m0 = mw * 64 + mf * 16;
                uint32_t addr = Abase + (uint32_t)m0 * (ASTR * 4) +
                                (uint32_t)kk * 4 + lds_off;
                uint32_t r0, r1, r2, r3;
                ldsm4(r0, r1, r2, r3, addr);
                afr[mf][0] = r0; afr[mf][1] = r2;
                afr[mf][2] = r1; afr[mf][3] = r3;
            }
            uint32_t bfr[4][2];
#pragma unroll
            for (int nf = 0; nf < 4; ++nf) {
                int n0 = nw * 32 + nf * 8;
                bfr[nf][0] = Bs[(kk + tig) * BSTR + n0 + grp];
                bfr[nf][1] = Bs[(kk + tig + 4) * BSTR + n0 + grp];
            }
#pragma unroll
            for (int mf = 0; mf < 4; ++mf)
#pragma unroll
                for (int nf = 0; nf < 4; ++nf)
                    mma_tf32(acc[mf][nf], afr[mf], bfr[nf]);
        }
    }
    __syncthreads();

    // ---- epilogue: regs -> smem transpose (+bias, tf32 round) -> scatter ----
    const int qsel = om >> 8;
    float* gout = g_qkv + (size_t)qsel * QKV_PLANE;
    float* st   = reinterpret_cast<float*>(buf);  // st[n_local][132]

    const int n_loc = tid & 63;
    const int qg    = tid >> 6;
    const int mm0   = om & 255;

#pragma unroll
    for (int h = 0; h < 2; ++h) {
        if ((nw >> 1) == h) {
#pragma unroll
            for (int mf = 0; mf < 4; ++mf) {
#pragma unroll
                for (int nf = 0; nf < 4; ++nf) {
#pragma unroll
                    for (int ci = 0; ci < 4; ++ci) {
                        int m = mw * 64 + mf * 16 + grp + ((ci >> 1) << 3);
                        int n = nw * 32 + nf * 8 + tig * 2 + (ci & 1);
                        st[(n - h * 64) * 132 + m] =
                            f2tf32f(acc[mf][nf][ci] + bias_s[m]);
                    }
                }
            }
        }
        __syncthreads();

        const int n = h * 64 + n_loc;
        const int so_base = wbs[n];
#pragma unroll
        for (int mg = 0; mg < 8; ++mg) {
            int m4 = qg * 32 + mg * 4;
            float4 v = *reinterpret_cast<const float4*>(st + n_loc * 132 + m4);
            int mm = mm0 + m4;
            *reinterpret_cast<float4*>(gout + (mm >> 5) * WINSTR + so_base + (mm & 31)) = v;
        }
        __syncthreads();
    }
}

// =====================================================================
// Kernel 2: per-(window, head) attention, tf32 mma.sync with ldmatrix
//   fragment loads. 128 threads; warp w owns query rows 16w..16w+15.
// =====================================================================
__global__ __launch_bounds__(128) void win_attn(float* __restrict__ out)
{
    __shared__ __align__(16) float Qs[64 * 36];       // Q[tok][d]; reused as Os
    __shared__ __align__(16) float Ks[56 * 36];       // K[tok][d]
    __shared__ __align__(16) float Ps[64 * 60];       // P[row][key]
    __shared__ __align__(16) float Vt[32 * 60 + 16];  // V^T: [d][key] (+pad: ldsm
                                                      // vb[3] over-reads 16B on last row)

    const int bid  = blockIdx.x;                  // window*8 + head
    const int widx = bid >> 3;
    const int head = bid & 7;
    const int b    = widx >> 10;
    const int hn   = (widx >> 5) & 31;
    const int wn   = widx & 31;
    const int tid  = threadIdx.x;
    const int wid  = tid >> 5;
    const int lane = tid & 31;
    const int grp  = lane >> 2;
    const int tig  = lane & 3;

    // ---- stage (g_qkv already tf32-rounded; pure copy) ----
    {
        const float4* q4 = reinterpret_cast<const float4*>(g_qkv + (size_t)bid * WINSTR);
        const float4* k4 = reinterpret_cast<const float4*>(g_qkv + QKV_PLANE + (size_t)bid * WINSTR);
        const float4* v4 = reinterpret_cast<const float4*>(g_qkv + 2 * QKV_PLANE + (size_t)bid * WINSTR);
        for (int i = tid; i < 392; i += 128) {
            int tok = i >> 3, d4 = (i & 7) * 4;
            *reinterpret_cast<float4*>(Qs + tok * 36 + d4) = q4[i];
            *reinterpret_cast<float4*>(Ks + tok * 36 + d4) = k4[i];
            float4 vv = v4[i];
            Vt[(d4 + 0) * 60 + tok] = vv.x;
            Vt[(d4 + 1) * 60 + tok] = vv.y;
            Vt[(d4 + 2) * 60 + tok] = vv.z;
            Vt[(d4 + 3) * 60 + tok] = vv.w;
        }
        for (int i = tid; i < 32 * 7; i += 128) { // zero V^T keys 49..55
            int d = i / 7, k = 49 + (i - d * 7);
            Vt[d * 60 + k] = 0.f;
        }
    }
    __syncthreads();

    const int m0 = wid * 16;
    const uint32_t qbase = smaddr(Qs), kbase = smaddr(Ks);
    const uint32_t pbase = smaddr(Ps), vbase = smaddr(Vt);
    const uint32_t arow  = (uint32_t)((lane & 7) + ((lane >> 4) << 3));
    const uint32_t ahalf = (uint32_t)(((lane >> 3) & 1) * 16);
    const uint32_t brow  = (uint32_t)(lane & 7);
    const uint32_t bquad = (uint32_t)(lane >> 3);

    // ---- A-frags of Q (all 4 k-steps) ----
    uint32_t qa[4][4];
#pragma unroll
    for (int ks = 0; ks < 4; ++ks) {
        uint32_t r0, r1, r2, r3;
        ldsm4(r0, r1, r2, r3, qbase + (m0 + arow) * 144 + ahalf + ks * 32);
        qa[ks][0] = r0; qa[ks][1] = r2; qa[ks][2] = r1; qa[ks][3] = r3;
    }

    // ---- S = Q*K^T : per nf, 2 ldsm4 give B-frags for all 4 k-steps ----
    float c[7][4];
#pragma unroll
    for (int nf = 0; nf < 7; ++nf) {
#pragma unroll
        for (int r = 0; r < 4; ++r) c[nf][r] = 0.f;
        uint32_t kaddr = kbase + (nf * 8 + brow) * 144 + bquad * 16;
        uint32_t r0, r1, r2, r3, s0, s1, s2, s3;
        ldsm4(r0, r1, r2, r3, kaddr);             // k 0..15
        ldsm4(s0, s1, s2, s3, kaddr + 64);        // k 16..31
        uint32_t bf[2];
        bf[0] = r0; bf[1] = r1; mma_tf32(c[nf], qa[0], bf);
        bf[0] = r2; bf[1] = r3; mma_tf32(c[nf], qa[1], bf);
        bf[0] = s0; bf[1] = s1; mma_tf32(c[nf], qa[2], bf);
        bf[0] = s2; bf[1] = s3; mma_tf32(c[nf], qa[3], bf);
    }

    // ---- mask pad cols, row max ----
    float mA = -1e30f, mB = -1e30f;
#pragma unroll
    for (int nf = 0; nf < 7; ++nf) {
        int col0 = nf * 8 + tig * 2;
        if (col0 > 48) { c[nf][0] = -1e30f; c[nf][2] = -1e30f; }
        if (col0 + 1 > 48) { c[nf][1] = -1e30f; c[nf][3] = -1e30f; }
        mA = fmaxf(mA, fmaxf(c[nf][0], c[nf][1]));
        mB = fmaxf(mB, fmaxf(c[nf][2], c[nf][3]));
    }
    mA = fmaxf(mA, __shfl_xor_sync(0xFFFFFFFF, mA, 1));
    mA = fmaxf(mA, __shfl_xor_sync(0xFFFFFFFF, mA, 2));
    mB = fmaxf(mB, __shfl_xor_sync(0xFFFFFFFF, mB, 1));
    mB = fmaxf(mB, __shfl_xor_sync(0xFFFFFFFF, mB, 2));

    // ---- exp + row sums + store P (tf32, paired stores) ----
    float sA = 0.f, sB = 0.f;
#pragma unroll
    for (int nf = 0; nf < 7; ++nf) {
        int col0 = nf * 8 + tig * 2;
        float e0 = fexp_scaled(c[nf][0] - mA);
        float e1 = fexp_scaled(c[nf][1] - mA);
        float e2 = fexp_scaled(c[nf][2] - mB);
        float e3 = fexp_scaled(c[nf][3] - mB);
        sA += e0 + e1;
        sB += e2 + e3;
        *reinterpret_cast<float2*>(Ps + (m0 + grp) * 60 + col0) =
            make_float2(f2tf32f(e0), f2tf32f(e1));
        *reinterpret_cast<float2*>(Ps + (m0 + grp + 8) * 60 + col0) =
            make_float2(f2tf32f(e2), f2tf32f(e3));
    }
    sA += __shfl_xor_sync(0xFFFFFFFF, sA, 1);
    sA += __shfl_xor_sync(0xFFFFFFFF, sA, 2);
    sB += __shfl_xor_sync(0xFFFFFFFF, sB, 1);
    sB += __shfl_xor_sync(0xFFFFFFFF, sB, 2);
    const float rA = 1.f / sA, rB = 1.f / sB;
    __syncwarp();

    // ---- A-frags of P (7 k-steps) ----
    uint32_t pa[7][4];
#pragma unroll
    for (int ks = 0; ks < 7; ++ks) {
        uint32_t r0, r1, r2, r3;
        ldsm4(r0, r1, r2, r3, pbase + (m0 + arow) * 240 + ahalf + ks * 32);
        pa[ks][0] = r0; pa[ks][1] = r2; pa[ks][2] = r1; pa[ks][3] = r3;
    }

    // ---- O = P*V : per nf (d-group), 4 ldsm4 give B-frags for 8 k-steps ----
    float o[4][4];
#pragma unroll
    for (int nf = 0; nf < 4; ++nf) {
#pragma unroll
        for (int r = 0; r < 4; ++r) o[nf][r] = 0.f;
        uint32_t vb[4][4];
#pragma unroll
        for (int pr = 0; pr < 4; ++pr) {
            ldsm4(vb[pr][0], vb[pr][1], vb[pr][2], vb[pr][3],
                  vbase + (nf * 8 + brow) * 240 + bquad * 16 + pr * 64);
        }
#pragma unroll
        for (int ks = 0; ks < 7; ++ks) {
            uint32_t bf[2];
            bf[0] = vb[ks >> 1][(ks & 1) * 2];
            bf[1] = vb[ks >> 1][(ks & 1) * 2 + 1];
            mma_tf32(o[nf], pa[ks], bf);
        }
    }
    __syncthreads();                              // all Qs reads complete

    // ---- normalize + stage O[row][d] into Qs region (stride 33) ----
    float* Os = Qs;
#pragma unroll
    for (int nf = 0; nf < 4; ++nf) {
        int col = nf * 8 + tig * 2;
        Os[(m0 + grp) * 33 + col]     = o[nf][0] * rA;
        Os[(m0 + grp) * 33 + col + 1] = o[nf][1] * rA;
        Os[(m0 + grp + 8) * 33 + col]     = o[nf][2] * rB;
        Os[(m0 + grp + 8) * 33 + col + 1] = o[nf][3] * rB;
    }
    __syncthreads();

    // ---- global write with inverse roll; coalesced 7-float runs ----
    const int h0 = hn * WSZ, w0 = wn * WSZ;
    float* ob = out + ((size_t)b * CCH + head * HD) * HW;
    for (int idx = tid; idx < WINSTR; idx += 128) {
        int d   = idx / WS2;
        int tok = idx - d * WS2;
        int ri  = tok / WSZ, ci = tok - ri * WSZ;
        int h = h0 + ri + SHIFTV; if (h >= HH) h -= HH;
        int w = w0 + ci + SHIFTV; if (w >= HH) w -= HH;
        ob[(size_t)d * HW + h * HH + w] = Os[tok * 33 + d];
    }
}

// =====================================================================
extern "C" void kernel_launch(void* const* d_in, const int* in_sizes, int n_in,
                              void* d_out, int out_size)
{
    const float* x  = (const float*)d_in[0];   // [4,256,224,224]
    const float* wq = (const float*)d_in[1];   // [768,256]
    const float* bq = (const float*)d_in[2];   // [768]
    float* out = (float*)d_out;                // [4,256,224,224]

    cvt_x<<<12544, 256>>>(x);
    cvt_w<<<192, 256>>>(wq);
    dim3 ggrid(6, 1568);                       // m-tiles fastest -> x reused in L2
    qkv_gemm<<<ggrid, 256>>>(bq);
    win_attn<<<32768, 128>>>(out);
}

// round 17
// speedup vs baseline: 2.4025x; 1.4075x over previous
#include <cuda_runtime.h>
#include <cuda_fp16.h>
#include <cstdint>

// ---------------- problem constants ----------------
#define BB     4
#define CCH    256
#define HH     224
#define HW     50176        // 224*224
#define WSZ    7
#define SHIFTV 3
#define NHEAD  8
#define HD     32
#define WS2    49
#define WINSTR 1568         // 49*32 elements per (window,head)
static constexpr size_t QKV_PLANE = 51380224ull;   // one of q/k/v

// scratch: q,k,v (fp16) in window-major [3][b][hn][wn][head][tok][d]
static __device__ __half g_qkv[3ull * QKV_PLANE];          // 308 MB
static __device__ __half g_xh[(size_t)BB * CCH * HW];      // fp16 x (103 MB)
static __device__ __half g_wh[768 * 256];                  // fp16 w_qkv

__device__ __forceinline__ uint32_t f2tf32(float f) {
    uint32_t r;
    asm("cvt.rna.tf32.f32 %0, %1;" : "=r"(r) : "f"(f));
    return r;
}
__device__ __forceinline__ float f2tf32f(float f) {
    return __uint_as_float(f2tf32(f));
}
__device__ __forceinline__ uint32_t f2h2(float lo, float hi) {
    uint32_t r;
    asm("cvt.rn.f16x2.f32 %0, %1, %2;" : "=r"(r) : "f"(hi), "f"(lo));
    return r;
}
__device__ __forceinline__ float2 h2f2(uint32_t h) {
    __half2 v = *reinterpret_cast<__half2*>(&h);
    return __half22float2(v);
}
__device__ __forceinline__ void mma_f16(float* c, const uint32_t* a,
                                        const uint32_t* b) {
    asm volatile(
        "mma.sync.aligned.m16n8k16.row.col.f32.f16.f16.f32 "
        "{%0,%1,%2,%3}, {%4,%5,%6,%7}, {%8,%9}, {%0,%1,%2,%3};"
        : "+f"(c[0]), "+f"(c[1]), "+f"(c[2]), "+f"(c[3])
        : "r"(a[0]), "r"(a[1]), "r"(a[2]), "r"(a[3]), "r"(b[0]), "r"(b[1]));
}
__device__ __forceinline__ void mma_tf32(float* c, const uint32_t* a,
                                         const uint32_t* b) {
    asm volatile(
        "mma.sync.aligned.m16n8k8.row.col.f32.tf32.tf32.f32 "
        "{%0,%1,%2,%3}, {%4,%5,%6,%7}, {%8,%9}, {%0,%1,%2,%3};"
        : "+f"(c[0]), "+f"(c[1]), "+f"(c[2]), "+f"(c[3])
        : "r"(a[0]), "r"(a[1]), "r"(a[2]), "r"(a[3]), "r"(b[0]), "r"(b[1]));
}
__device__ __forceinline__ uint32_t smaddr(const void* p) {
    uint32_t a;
    asm("{ .reg .u64 t; cvta.to.shared.u64 t, %1; cvt.u32.u64 %0, t; }"
        : "=r"(a) : "l"(p));
    return a;
}
__device__ __forceinline__ void cp16(uint32_t d, const void* s) {
    asm volatile("cp.async.ca.shared.global [%0], [%1], 16;" :: "r"(d), "l"(s));
}
#define CP_COMMIT() asm volatile("cp.async.commit_group;" ::: "memory")
#define CP_WAIT0()  asm volatile("cp.async.wait_group 0;" ::: "memory")
__device__ __forceinline__ void ldsm4(uint32_t& r0, uint32_t& r1,
                                      uint32_t& r2, uint32_t& r3, uint32_t a) {
    asm volatile("ldmatrix.sync.aligned.m8n8.x4.shared.b16 {%0,%1,%2,%3}, [%4];"
                 : "=r"(r0), "=r"(r1), "=r"(r2), "=r"(r3) : "r"(a));
}
__device__ __forceinline__ void ldsm4t(uint32_t& r0, uint32_t& r1,
                                       uint32_t& r2, uint32_t& r3, uint32_t a) {
    asm volatile("ldmatrix.sync.aligned.m8n8.x4.trans.shared.b16 {%0,%1,%2,%3}, [%4];"
                 : "=r"(r0), "=r"(r1), "=r"(r2), "=r"(r3) : "r"(a));
}

// fast exp2-based exp((s-mx)*scale): FMA-pipe only (no MUFU)
__device__ __forceinline__ float fexp_scaled(float sm_diff) {
    const float C = 0.17677669529663687f * 1.4426950408889634f;  // scale*log2e
    float y = sm_diff * C;
    y = fmaxf(y, -100.0f);
    float z = y + 12582912.0f;
    float n = z - 12582912.0f;
    float f = y - n;
    int ni = __float_as_int(z) - 0x4B400000;
    float p = 0.0013333558146428443f;
    p = fmaf(p, f, 0.009618129107628477f);
    p = fmaf(p, f, 0.05550410866482158f);
    p = fmaf(p, f, 0.2402265069591007f);
    p = fmaf(p, f, 0.6931471805599453f);
    p = fmaf(p, f, 1.0f);
    return __int_as_float(__float_as_int(p) + (ni << 23));
}

// =====================================================================
// Pre-pass: contiguous fp16 converts.
// =====================================================================
__global__ void cvt_x(const float* __restrict__ x) {
    const size_t n4 = (size_t)BB * CCH * HW / 4;
    const float4* s = reinterpret_cast<const float4*>(x);
    uint2* d = reinterpret_cast<uint2*>(g_xh);
    for (size_t i = (size_t)blockIdx.x * blockDim.x + threadIdx.x; i < n4;
         i += (size_t)gridDim.x * blockDim.x) {
        float4 v = s[i];
        d[i] = make_uint2(f2h2(v.x, v.y), f2h2(v.z, v.w));
    }
}
__global__ void cvt_w(const float* __restrict__ w) {
    int i = blockIdx.x * blockDim.x + threadIdx.x;
    if (i < 768 * 256 / 4) {
        float4 v = reinterpret_cast<const float4*>(w)[i];
        reinterpret_cast<uint2*>(g_wh)[i] =
            make_uint2(f2h2(v.x, v.y), f2h2(v.z, v.w));
    }
}

// =====================================================================
// Kernel 1: QKV GEMM, fp16 m16n8k16 mma.sync + cp.async double buffering.
//   CTA tile M=128 x N=128, kb=16, K=256 (16 k-tiles).
//   A: [m][k] halfs stride 48B (ldsm frags); B: [k][n] halfs stride 272B
//   (ldsm.trans frags). Epilogue: f32 acc + bias -> fp16 g_qkv scatter.
// =====================================================================
#define TILE_B 10496           // bytes per buffer: 128*48 + 16*272

__global__ __launch_bounds__(256) void qkv_gemm(const float* __restrict__ bq)
{
    // 33.8KB: 2 fp16 tile buffers (21KB) | epilogue 64x132 f32 staging
    __shared__ __align__(16) uint32_t buf[8448];
    __shared__ int   wbs[128];
    __shared__ float bias_s[128];

    const int mt  = blockIdx.x;                   // 0..5
    const int pt  = blockIdx.y;                   // 0..1567
    const int b   = pt / 392;
    const int p0  = (pt - b * 392) * 128;
    const int om  = mt * 128;
    const int tid = threadIdx.x;
    const int wid = tid >> 5;
    const int lane = tid & 31;

    if (tid < 128) {
        int p  = p0 + tid;
        int h  = p / HH, w = p - h * HH;
        int hx = h - SHIFTV; if (hx < 0) hx += HH;   // shifted-back coords
        int wx = w - SHIFTV; if (wx < 0) wx += HH;
        int hn = hx / WSZ, ri = hx - hn * WSZ;
        int wn = wx / WSZ, ci = wx - wn * WSZ;
        int widx = (b * 32 + hn) * 32 + wn;
        wbs[tid]    = widx * 8 * WINSTR + (ri * WSZ + ci) * HD;
        bias_s[tid] = bq[om + tid];
    }
    __syncthreads();

    const uint32_t buf_base = smaddr(buf);

    auto issue = [&](int kt, int sel) {
        const int kc = kt * 16;
        {   // A: 256 x 16B chunks, [m][k] stride 48B (32B data)
            int m = tid >> 1, q = tid & 1;
            cp16(buf_base + (uint32_t)(sel * TILE_B + m * 48 + q * 16),
                 g_wh + (size_t)(om + m) * 256 + kc + q * 8);
        }
        {   // B: 256 x 16B chunks, [k][n] stride 272B (256B data)
            int k = tid >> 4, n8 = (tid & 15) * 8;
            cp16(buf_base + (uint32_t)(sel * TILE_B + 6144 + k * 272 + n8 * 2),
                 g_xh + (size_t)(b * CCH + kc + k) * HW + p0 + n8);
        }
        CP_COMMIT();
    };

    const int mw = wid & 1;
    const int nw = wid >> 1;
    const int grp = lane >> 2;
    const int tig = lane & 3;

    // ldsm lane constants: row = (l&7)+((l>>3)&1)*8, halfcol = (l>>4)*16B
    const uint32_t lrow  = (uint32_t)((lane & 7) + ((lane >> 3) & 1) * 8);
    const uint32_t lhalf = (uint32_t)((lane >> 4) * 16);
    const uint32_t aoff  = lrow * 48 + lhalf;
    const uint32_t boff  = lrow * 272 + lhalf;

    float acc[4][4][4];
#pragma unroll
    for (int i = 0; i < 4; ++i)
#pragma unroll
        for (int j = 0; j < 4; ++j)
#pragma unroll
            for (int r = 0; r < 4; ++r) acc[i][j][r] = 0.f;

    issue(0, 0);

    for (int kt = 0; kt < 16; ++kt) {
        CP_WAIT0();
        __syncthreads();
        if (kt < 15) issue(kt + 1, (kt + 1) & 1);

        const uint32_t Abase = buf_base + (uint32_t)((kt & 1) * TILE_B);
        const uint32_t Bbase = Abase + 6144;

        uint32_t afr[4][4];
#pragma unroll
        for (int mf = 0; mf < 4; ++mf)
            ldsm4(afr[mf][0], afr[mf][1], afr[mf][2], afr[mf][3],
                  Abase + (uint32_t)(mw * 64 + mf * 16) * 48 + aoff);

        uint32_t bfr[2][4];
#pragma unroll
        for (int np = 0; np < 2; ++np)
            ldsm4t(bfr[np][0], bfr[np][1], bfr[np][2], bfr[np][3],
                   Bbase + boff + (uint32_t)(nw * 32 + np * 16) * 2);

#pragma unroll
        for (int mf = 0; mf < 4; ++mf) {
            mma_f16(acc[mf][0], afr[mf], &bfr[0][0]);
            mma_f16(acc[mf][1], afr[mf], &bfr[0][2]);
            mma_f16(acc[mf][2], afr[mf], &bfr[1][0]);
            mma_f16(acc[mf][3], afr[mf], &bfr[1][2]);
        }
    }
    __syncthreads();

    // ---- epilogue: regs -> smem transpose (+bias) -> fp16 window scatter ----
    const int qsel = om >> 8;
    __half* gout = g_qkv + (size_t)qsel * QKV_PLANE;
    float* st    = reinterpret_cast<float*>(buf);  // st[n_local][132]

    const int n_loc = tid & 63;
    const int qg    = tid >> 6;
    const int mm0   = om & 255;

#pragma unroll
    for (int h = 0; h < 2; ++h) {
        if ((nw >> 1) == h) {
#pragma unroll
            for (int mf = 0; mf < 4; ++mf) {
#pragma unroll
                for (int nf = 0; nf < 4; ++nf) {
#pragma unroll
                    for (int ci = 0; ci < 4; ++ci) {
                        int m = mw * 64 + mf * 16 + grp + ((ci >> 1) << 3);
                        int n = nw * 32 + nf * 8 + tig * 2 + (ci & 1);
                        st[(n - h * 64) * 132 + m] = acc[mf][nf][ci] + bias_s[m];
                    }
                }
            }
        }
        __syncthreads();

        const int n = h * 64 + n_loc;
        const int so_base = wbs[n];
#pragma unroll
        for (int mg = 0; mg < 4; ++mg) {
            int m8 = qg * 32 + mg * 8;
            float4 f0 = *reinterpret_cast<const float4*>(st + n_loc * 132 + m8);
            float4 f1 = *reinterpret_cast<const float4*>(st + n_loc * 132 + m8 + 4);
            uint4 hv = make_uint4(f2h2(f0.x, f0.y), f2h2(f0.z, f0.w),
                                  f2h2(f1.x, f1.y), f2h2(f1.z, f1.w));
            int mm = mm0 + m8;
            *reinterpret_cast<uint4*>(gout + (mm >> 5) * WINSTR + so_base + (mm & 31)) = hv;
        }
        __syncthreads();
    }
}

// =====================================================================
// Kernel 2: per-(window, head) attention, tf32 mma.sync with ldmatrix
//   fragment loads. fp16 staging; otab-based division-free writeout.
// =====================================================================
__global__ __launch_bounds__(128) void win_attn(float* __restrict__ out)
{
    __shared__ __align__(16) float Qs[64 * 36];       // Q[tok][d]; reused as Os
    __shared__ __align__(16) float Ks[56 * 36];       // K[tok][d]
    __shared__ __align__(16) float Ps[64 * 60];       // P[row][key]
    __shared__ __align__(16) float Vt[32 * 60 + 16];  // V^T [d][key] (+ldsm pad)
    __shared__ int otab[49];                          // rolled spatial offsets

    const int bid  = blockIdx.x;                  // window*8 + head
    const int widx = bid >> 3;
    const int head = bid & 7;
    const int b    = widx >> 10;
    const int hn   = (widx >> 5) & 31;
    const int wn   = widx & 31;
    const int tid  = threadIdx.x;
    const int wid  = tid >> 5;
    const int lane = tid & 31;
    const int grp  = lane >> 2;
    const int tig  = lane & 3;

    if (tid < 49) {                               // offset table (one-time divs)
        int ri = tid / WSZ, ci = tid - ri * WSZ;
        int h = hn * WSZ + ri + SHIFTV; if (h >= HH) h -= HH;
        int w = wn * WSZ + ci + SHIFTV; if (w >= HH) w -= HH;
        otab[tid] = h * HH + w;
    }

    // ---- stage fp16 -> f32 SMEM ----
    {
        const uint4* q4 = reinterpret_cast<const uint4*>(g_qkv + (size_t)bid * WINSTR);
        const uint4* k4 = reinterpret_cast<const uint4*>(g_qkv + QKV_PLANE + (size_t)bid * WINSTR);
        const uint4* v4 = reinterpret_cast<const uint4*>(g_qkv + 2 * QKV_PLANE + (size_t)bid * WINSTR);
        for (int i = tid; i < 196; i += 128) {    // 196 chunks of 8 halfs
            int tok = i >> 2, d8 = (i & 3) * 8;
            uint4 qv = q4[i];
            float2 a0 = h2f2(qv.x), a1 = h2f2(qv.y), a2 = h2f2(qv.z), a3 = h2f2(qv.w);
            *reinterpret_cast<float4*>(Qs + tok * 36 + d8)     = make_float4(a0.x, a0.y, a1.x, a1.y);
            *reinterpret_cast<float4*>(Qs + tok * 36 + d8 + 4) = make_float4(a2.x, a2.y, a3.x, a3.y);
            uint4 kv = k4[i];
            a0 = h2f2(kv.x); a1 = h2f2(kv.y); a2 = h2f2(kv.z); a3 = h2f2(kv.w);
            *reinterpret_cast<float4*>(Ks + tok * 36 + d8)     = make_float4(a0.x, a0.y, a1.x, a1.y);
            *reinterpret_cast<float4*>(Ks + tok * 36 + d8 + 4) = make_float4(a2.x, a2.y, a3.x, a3.y);
            uint4 vv = v4[i];
            a0 = h2f2(vv.x); a1 = h2f2(vv.y); a2 = h2f2(vv.z); a3 = h2f2(vv.w);
            Vt[(d8 + 0) * 60 + tok] = a0.x; Vt[(d8 + 1) * 60 + tok] = a0.y;
            Vt[(d8 + 2) * 60 + tok] = a1.x; Vt[(d8 + 3) * 60 + tok] = a1.y;
            Vt[(d8 + 4) * 60 + tok] = a2.x; Vt[(d8 + 5) * 60 + tok] = a2.y;
            Vt[(d8 + 6) * 60 + tok] = a3.x; Vt[(d8 + 7) * 60 + tok] = a3.y;
        }
        for (int i = tid; i < 32 * 7; i += 128) { // zero V^T keys 49..55
            int d = i / 7, k = 49 + (i - d * 7);
            Vt[d * 60 + k] = 0.f;
        }
    }
    __syncthreads();

    const int m0 = wid * 16;
    const uint32_t qbase = smaddr(Qs), kbase = smaddr(Ks);
    const uint32_t pbase = smaddr(Ps), vbase = smaddr(Vt);
    const uint32_t arow  = (uint32_t)((lane & 7) + ((lane >> 4) << 3));
    const uint32_t ahalf = (uint32_t)(((lane >> 3) & 1) * 16);
    const uint32_t brow  = (uint32_t)(lane & 7);
    const uint32_t bquad = (uint32_t)(lane >> 3);

    // ---- A-frags of Q (all 4 k-steps) ----
    uint32_t qa[4][4];
#pragma unroll
    for (int ks = 0; ks < 4; ++ks) {
        uint32_t r0, r1, r2, r3;
        ldsm4(r0, r1, r2, r3, qbase + (m0 + arow) * 144 + ahalf + ks * 32);
        qa[ks][0] = r0; qa[ks][1] = r2; qa[ks][2] = r1; qa[ks][3] = r3;
    }

    // ---- S = Q*K^T ----
    float c[7][4];
#pragma unroll
    for (int nf = 0; nf < 7; ++nf) {
#pragma unroll
        for (int r = 0; r < 4; ++r) c[nf][r] = 0.f;
        uint32_t kaddr = kbase + (nf * 8 + brow) * 144 + bquad * 16;
        uint32_t r0, r1, r2, r3, s0, s1, s2, s3;
        ldsm4(r0, r1, r2, r3, kaddr);             // k 0..15
        ldsm4(s0, s1, s2, s3, kaddr + 64);        // k 16..31
        uint32_t bf[2];
        bf[0] = r0; bf[1] = r1; mma_tf32(c[nf], qa[0], bf);
        bf[0] = r2; bf[1] = r3; mma_tf32(c[nf], qa[1], bf);
        bf[0] = s0; bf[1] = s1; mma_tf32(c[nf], qa[2], bf);
        bf[0] = s2; bf[1] = s3; mma_tf32(c[nf], qa[3], bf);
    }

    // ---- mask pad cols, row max ----
    float mA = -1e30f, mB = -1e30f;
#pragma unroll
    for (int nf = 0; nf < 7; ++nf) {
        int col0 = nf * 8 + tig * 2;
        if (col0 > 48) { c[nf][0] = -1e30f; c[nf][2] = -1e30f; }
        if (col0 + 1 > 48) { c[nf][1] = -1e30f; c[nf][3] = -1e30f; }
        mA = fmaxf(mA, fmaxf(c[nf][0], c[nf][1]));
        mB = fmaxf(mB, fmaxf(c[nf][2], c[nf][3]));
    }
    mA = fmaxf(mA, __shfl_xor_sync(0xFFFFFFFF, mA, 1));
    mA = fmaxf(mA, __shfl_xor_sync(0xFFFFFFFF, mA, 2));
    mB = fmaxf(mB, __shfl_xor_sync(0xFFFFFFFF, mB, 1));
    mB = fmaxf(mB, __shfl_xor_sync(0xFFFFFFFF, mB, 2));

    // ---- exp + row sums + store P (tf32, paired stores) ----
    float sA = 0.f, sB = 0.f;
#pragma unroll
    for (int nf = 0; nf < 7; ++nf) {
        int col0 = nf * 8 + tig * 2;
        float e0 = fexp_scaled(c[nf][0] - mA);
        float e1 = fexp_scaled(c[nf][1] - mA);
        float e2 = fexp_scaled(c[nf][2] - mB);
        float e3 = fexp_scaled(c[nf][3] - mB);
        sA += e0 + e1;
        sB += e2 + e3;
        *reinterpret_cast<float2*>(Ps + (m0 + grp) * 60 + col0) =
            make_float2(f2tf32f(e0), f2tf32f(e1));
        *reinterpret_cast<float2*>(Ps + (m0 + grp + 8) * 60 + col0) =
            make_float2(f2tf32f(e2), f2tf32f(e3));
    }
    sA += __shfl_xor_sync(0xFFFFFFFF, sA, 1);
    sA += __shfl_xor_sync(0xFFFFFFFF, sA, 2);
    sB += __shfl_xor_sync(0xFFFFFFFF, sB, 1);
    sB += __shfl_xor_sync(0xFFFFFFFF, sB, 2);
    const float rA = 1.f / sA, rB = 1.f / sB;
    __syncwarp();

    // ---- A-frags of P (7 k-steps) ----
    uint32_t pa[7][4];
#pragma unroll
    for (int ks = 0; ks < 7; ++ks) {
        uint32_t r0, r1, r2, r3;
        ldsm4(r0, r1, r2, r3, pbase + (m0 + arow) * 240 + ahalf + ks * 32);
        pa[ks][0] = r0; pa[ks][1] = r2; pa[ks][2] = r1; pa[ks][3] = r3;
    }

    // ---- O = P*V ----
    float o[4][4];
#pragma unroll
    for (int nf = 0; nf < 4; ++nf) {
#pragma unroll
        for (int r = 0; r < 4; ++r) o[nf][r] = 0.f;
        uint32_t vb[4][4];
#pragma unroll
        for (int pr = 0; pr < 4; ++pr) {
            ldsm4(vb[pr][0], vb[pr][1], vb[pr][2], vb[pr][3],
                  vbase + (nf * 8 + brow) * 240 + bquad * 16 + pr * 64);
        }
#pragma unroll
        for (int ks = 0; ks < 7; ++ks) {
            uint32_t bf[2];
            bf[0] = vb[ks >> 1][(ks & 1) * 2];
            bf[1] = vb[ks >> 1][(ks & 1) * 2 + 1];
            mma_tf32(o[nf], pa[ks], bf);
        }
    }
    __syncthreads();                              // all Qs reads complete

    // ---- normalize + stage O[row][d] into Qs region (stride 33) ----
    float* Os = Qs;
#pragma unroll
    for (int nf = 0; nf < 4; ++nf) {
        int col = nf * 8 + tig * 2;
        Os[(m0 + grp) * 33 + col]     = o[nf][0] * rA;
        Os[(m0 + grp) * 33 + col + 1] = o[nf][1] * rA;
        Os[(m0 + grp + 8) * 33 + col]     = o[nf][2] * rB;
        Os[(m0 + grp + 8) * 33 + col + 1] = o[nf][3] * rB;
    }
    __syncthreads();

    // ---- global write: division-free (d,tok) walk + otab offsets ----
    float* ob = out + ((size_t)b * CCH + head * HD) * HW;
    int d = 0, tok = tid;
    if (tok >= WS2) { tok -= WS2; d = 1; }
    if (tok >= WS2) { tok -= WS2; d = 2; }
    while (d < HD) {
        ob[d * HW + otab[tok]] = Os[tok * 33 + d];
        tok += 30; d += 2;                        // += 128 = 2*49 + 30
        if (tok >= WS2) { tok -= WS2; ++d; }
    }
}

// =====================================================================
extern "C" void kernel_launch(void* const* d_in, const int* in_sizes, int n_in,
                              void* d_out, int out_size)
{
    const float* x  = (const float*)d_in[0];   // [4,256,224,224]
    const float* wq = (const float*)d_in[1];   // [768,256]
    const float* bq = (const float*)d_in[2];   // [768]
    float* out = (float*)d_out;                // [4,256,224,224]

    cvt_x<<<12544, 256>>>(x);
    cvt_w<<<192, 256>>>(wq);
    dim3 ggrid(6, 1568);                       // m-tiles fastest -> x reused in L2
    qkv_gemm<<<ggrid, 256>>>(bq);
    win_attn<<<32768, 128>>>(out);
}